// round 3
// baseline (speedup 1.0000x reference)
#include <cuda_runtime.h>
#include <cstdint>

// Problem constants
#define B_SZ   1024
#define NE_SZ  100000
#define D_SZ   200      // DE = DR = DT = P = 200

// Scratch for H = ((R[r]F0) * (E[e1]F1) * (T[t]F3)) @ F2^T   (B x 200)
__device__ float g_H[B_SZ * D_SZ];

// ---------------------------------------------------------------------------
// Packed f32x2 helpers (Blackwell sm_100+)
// ---------------------------------------------------------------------------
__device__ __forceinline__ unsigned long long pack_dup(float x) {
    unsigned long long r;
    unsigned u = __float_as_uint(x);
    asm("mov.b64 %0, {%1, %1};" : "=l"(r) : "r"(u));
    return r;
}

__device__ __forceinline__ void ffma2(unsigned long long& d,
                                      unsigned long long a,
                                      unsigned long long b) {
    asm("fma.rn.f32x2 %0, %1, %2, %0;" : "+l"(d) : "l"(a), "l"(b));
}

__device__ __forceinline__ float2 unpack2(unsigned long long a) {
    unsigned lo, hi;
    asm("mov.b64 {%0, %1}, %2;" : "=r"(lo), "=r"(hi) : "l"(a));
    float2 f;
    f.x = __uint_as_float(lo);
    f.y = __uint_as_float(hi);
    return f;
}

// ---------------------------------------------------------------------------
// Kernel A: preprocessing.
//   G[b][p] = (R[r_idx[b]] @ F0)[p] * (E[e1_idx[b]] @ F1)[p] * (T[t_idx[b]] @ F3)[p]
//   H[b][j] = sum_p G[b][p] * F2[j][p]          (i.e. H = G @ F2^T)
// 128 blocks x 256 threads, 8 batch rows per block. ~164 MFLOP total.
// ---------------------------------------------------------------------------
#define ROWS_PER_BLK 8

__global__ __launch_bounds__(256)
void preproc_kernel(const int* __restrict__ e1_idx,
                    const int* __restrict__ r_idx,
                    const int* __restrict__ t_idx,
                    const float* __restrict__ E,
                    const float* __restrict__ R,
                    const float* __restrict__ T,
                    const float* __restrict__ F0,
                    const float* __restrict__ F1,
                    const float* __restrict__ F2,
                    const float* __restrict__ F3,
                    float* __restrict__ H)
{
    __shared__ float sE[ROWS_PER_BLK][D_SZ];
    __shared__ float sR[ROWS_PER_BLK][D_SZ];
    __shared__ float sT[ROWS_PER_BLK][D_SZ];
    __shared__ float sG[ROWS_PER_BLK][D_SZ];

    const int b0  = blockIdx.x * ROWS_PER_BLK;
    const int tid = threadIdx.x;

    // Load the 8 embedding rows for this block into smem
    for (int r = 0; r < ROWS_PER_BLK; r++) {
        const int be = e1_idx[b0 + r];
        const int br = r_idx[b0 + r];
        const int bt = t_idx[b0 + r];
        for (int k = tid; k < D_SZ; k += 256) {
            sE[r][k] = E[(size_t)be * D_SZ + k];
            sR[r][k] = R[(size_t)br * D_SZ + k];
            sT[r][k] = T[(size_t)bt * D_SZ + k];
        }
    }
    __syncthreads();

    // G phase: tasks = 8 rows x 200 p-values.
    // F*[k*200+p] access is coalesced across the warp (consecutive p).
    for (int task = tid; task < ROWS_PER_BLK * D_SZ; task += 256) {
        const int r = task / D_SZ;
        const int p = task % D_SZ;
        float fr = 0.f, fe = 0.f, ft = 0.f;
        #pragma unroll 4
        for (int k = 0; k < D_SZ; k++) {
            fr = fmaf(sR[r][k], F0[k * D_SZ + p], fr);
            fe = fmaf(sE[r][k], F1[k * D_SZ + p], fe);
            ft = fmaf(sT[r][k], F3[k * D_SZ + p], ft);
        }
        sG[r][p] = fr * fe * ft;
    }
    __syncthreads();

    // H phase: H[b][j] = sum_p G[b][p] * F2[j][p]
    // sG[r][p] is a warp-wide broadcast (same address all lanes); F2 row per thread.
    for (int task = tid; task < ROWS_PER_BLK * D_SZ; task += 256) {
        const int r = task / D_SZ;
        const int j = task % D_SZ;
        float acc = 0.f;
        const float4* f2row = reinterpret_cast<const float4*>(F2 + (size_t)j * D_SZ);
        const float* g = sG[r];
        #pragma unroll 5
        for (int p4 = 0; p4 < D_SZ / 4; p4++) {
            float4 f = f2row[p4];
            acc = fmaf(g[p4 * 4 + 0], f.x, acc);
            acc = fmaf(g[p4 * 4 + 1], f.y, acc);
            acc = fmaf(g[p4 * 4 + 2], f.z, acc);
            acc = fmaf(g[p4 * 4 + 3], f.w, acc);
        }
        H[(size_t)(b0 + r) * D_SZ + j] = acc;
    }
}

// ---------------------------------------------------------------------------
// Kernel B: x = sigmoid(H @ E^T),  M=1024, N=100000, K=200, fp32.
// 128x128 block tile, BK=8 (25 k-iters, exact), 256 threads, 8x8 per thread.
// Inner product uses packed fma.rn.f32x2 (2 FMAs per fma-pipe issue).
// Grid = (8 m-tiles, 782 n-tiles): all 8 m-tiles of one E column strip run in
// the same wave -> E tile is L2-resident and read ~once from DRAM.
// ---------------------------------------------------------------------------
#define BM 128
#define BN 128
#define BK 8
#define KITERS (D_SZ / BK)   // 25

__global__ __launch_bounds__(256, 2)
void gemm_sigmoid_kernel(const float* __restrict__ H,
                         const float* __restrict__ E,
                         float* __restrict__ out)
{
    const int m0 = blockIdx.x * BM;   // 0..7  -> 0..896
    const int n0 = blockIdx.y * BN;   // 0..781

    __shared__ __align__(16) float As[2][BK][BM];
    __shared__ __align__(16) float Bs[2][BK][BN];

    const int tid = threadIdx.x;
    const int tx  = tid & 15;   // n direction (0..15)
    const int ty  = tid >> 4;   // m direction (0..15)

    // global->smem load mapping: thread t loads one float4 of H and one of E
    const int lrow = tid >> 1;          // 0..127
    const int lk   = (tid & 1) * 4;     // 0 or 4

    const float* hptr = H + (size_t)(m0 + lrow) * D_SZ + lk;
    const int    nrow = n0 + lrow;
    const bool   nvalid = (nrow < NE_SZ);
    const float* eptr = E + (size_t)(nvalid ? nrow : 0) * D_SZ + lk;

    unsigned long long acc[8][4];
    #pragma unroll
    for (int i = 0; i < 8; i++)
        #pragma unroll
        for (int j = 0; j < 4; j++) acc[i][j] = 0ull;

    // prologue: load k-chunk 0
    float4 aReg = *reinterpret_cast<const float4*>(hptr);
    float4 bReg = nvalid ? *reinterpret_cast<const float4*>(eptr)
                         : make_float4(0.f, 0.f, 0.f, 0.f);
    As[0][lk + 0][lrow] = aReg.x; As[0][lk + 1][lrow] = aReg.y;
    As[0][lk + 2][lrow] = aReg.z; As[0][lk + 3][lrow] = aReg.w;
    Bs[0][lk + 0][lrow] = bReg.x; Bs[0][lk + 1][lrow] = bReg.y;
    Bs[0][lk + 2][lrow] = bReg.z; Bs[0][lk + 3][lrow] = bReg.w;
    __syncthreads();

    int buf = 0;
    for (int kt = 0; kt < KITERS; kt++) {
        // prefetch next k-chunk into registers
        if (kt < KITERS - 1) {
            aReg = *reinterpret_cast<const float4*>(hptr + (kt + 1) * BK);
            bReg = nvalid ? *reinterpret_cast<const float4*>(eptr + (kt + 1) * BK)
                          : make_float4(0.f, 0.f, 0.f, 0.f);
        }

        #pragma unroll
        for (int kk = 0; kk < BK; kk++) {
            const float4 a0 = *reinterpret_cast<const float4*>(&As[buf][kk][ty * 8]);
            const float4 a1 = *reinterpret_cast<const float4*>(&As[buf][kk][ty * 8 + 4]);
            const unsigned long long* bp =
                reinterpret_cast<const unsigned long long*>(&Bs[buf][kk][tx * 8]);
            const unsigned long long b0 = bp[0], b1 = bp[1], b2 = bp[2], b3 = bp[3];

            unsigned long long ad[8];
            ad[0] = pack_dup(a0.x); ad[1] = pack_dup(a0.y);
            ad[2] = pack_dup(a0.z); ad[3] = pack_dup(a0.w);
            ad[4] = pack_dup(a1.x); ad[5] = pack_dup(a1.y);
            ad[6] = pack_dup(a1.z); ad[7] = pack_dup(a1.w);

            #pragma unroll
            for (int i = 0; i < 8; i++) {
                ffma2(acc[i][0], ad[i], b0);
                ffma2(acc[i][1], ad[i], b1);
                ffma2(acc[i][2], ad[i], b2);
                ffma2(acc[i][3], ad[i], b3);
            }
        }

        if (kt < KITERS - 1) {
            const int nb = buf ^ 1;
            As[nb][lk + 0][lrow] = aReg.x; As[nb][lk + 1][lrow] = aReg.y;
            As[nb][lk + 2][lrow] = aReg.z; As[nb][lk + 3][lrow] = aReg.w;
            Bs[nb][lk + 0][lrow] = bReg.x; Bs[nb][lk + 1][lrow] = bReg.y;
            Bs[nb][lk + 2][lrow] = bReg.z; Bs[nb][lk + 3][lrow] = bReg.w;
            __syncthreads();
            buf = nb;
        }
    }

    // epilogue: sigmoid + store
    #pragma unroll
    for (int i = 0; i < 8; i++) {
        const int m = m0 + ty * 8 + i;           // always < 1024
        const int n = n0 + tx * 8;
        float v[8];
        #pragma unroll
        for (int j2 = 0; j2 < 4; j2++) {
            float2 p = unpack2(acc[i][j2]);
            v[2 * j2 + 0] = p.x;
            v[2 * j2 + 1] = p.y;
        }
        #pragma unroll
        for (int j = 0; j < 8; j++)
            v[j] = 1.0f / (1.0f + __expf(-v[j]));

        float* orow = out + (size_t)m * NE_SZ + n;
        if (n + 8 <= NE_SZ) {
            float4 o0 = make_float4(v[0], v[1], v[2], v[3]);
            float4 o1 = make_float4(v[4], v[5], v[6], v[7]);
            *reinterpret_cast<float4*>(orow)     = o0;
            *reinterpret_cast<float4*>(orow + 4) = o1;
        } else {
            for (int j = 0; j < 8; j++)
                if (n + j < NE_SZ) orow[j] = v[j];
        }
    }
}

// ---------------------------------------------------------------------------
// Launch. Input order per metadata: e1_idx, r_idx, t_idx, E, R, T, F0, F1, F2, F3
// ---------------------------------------------------------------------------
extern "C" void kernel_launch(void* const* d_in, const int* in_sizes, int n_in,
                              void* d_out, int out_size)
{
    const int*   e1_idx = (const int*)d_in[0];
    const int*   r_idx  = (const int*)d_in[1];
    const int*   t_idx  = (const int*)d_in[2];
    const float* E      = (const float*)d_in[3];
    const float* R      = (const float*)d_in[4];
    const float* T      = (const float*)d_in[5];
    const float* F0     = (const float*)d_in[6];
    const float* F1     = (const float*)d_in[7];
    const float* F2     = (const float*)d_in[8];
    const float* F3     = (const float*)d_in[9];
    float*       out    = (float*)d_out;

    float* H = nullptr;
    cudaGetSymbolAddress((void**)&H, g_H);

    preproc_kernel<<<B_SZ / ROWS_PER_BLK, 256>>>(
        e1_idx, r_idx, t_idx, E, R, T, F0, F1, F2, F3, H);

    dim3 grid(B_SZ / BM, (NE_SZ + BN - 1) / BN);   // (8, 782)
    gemm_sigmoid_kernel<<<grid, 256>>>(H, E, out);
}

// round 4
// speedup vs baseline: 2.2181x; 2.2181x over previous
#include <cuda_runtime.h>
#include <cstdint>

// Problem constants
#define B_SZ   1024
#define NE_SZ  100000
#define D_SZ   200      // DE = DR = DT = P = 200

// Scratch: H = ((R[r]F0) * (E[e1]F1) * (T[t]F3)) @ F2^T   (B x 200)
__device__ float g_H[B_SZ * D_SZ];
// Scratch: F2 transposed (P-major) so the H phase is coalesced
__device__ float g_F2T[D_SZ * D_SZ];

// ---------------------------------------------------------------------------
// Packed f32x2 helpers (Blackwell sm_100+)
// ---------------------------------------------------------------------------
__device__ __forceinline__ void ffma2(unsigned long long& d,
                                      unsigned long long a,
                                      unsigned long long b) {
    asm("fma.rn.f32x2 %0, %1, %2, %0;" : "+l"(d) : "l"(a), "l"(b));
}

__device__ __forceinline__ float2 unpack2(unsigned long long a) {
    unsigned lo, hi;
    asm("mov.b64 {%0, %1}, %2;" : "=r"(lo), "=r"(hi) : "l"(a));
    float2 f;
    f.x = __uint_as_float(lo);
    f.y = __uint_as_float(hi);
    return f;
}

// ---------------------------------------------------------------------------
// Kernel 0: F2T[p][j] = F2[j][p]   (160 KB, one-shot)
// ---------------------------------------------------------------------------
__global__ __launch_bounds__(256)
void transpose_f2_kernel(const float* __restrict__ F2, float* __restrict__ F2T)
{
    int idx = blockIdx.x * 256 + threadIdx.x;
    if (idx < D_SZ * D_SZ) {
        int p = idx / D_SZ;
        int j = idx - p * D_SZ;
        F2T[idx] = F2[j * D_SZ + p];
    }
}

// ---------------------------------------------------------------------------
// Kernel 1: preprocessing (fully coalesced both phases).
//   G[b][p] = (R[r]F0)[p] * (E[e1]F1)[p] * (T[t]F3)[p]
//   H[b][j] = sum_p G[b][p] * F2T[p][j]
// 256 blocks x 256 threads, 4 rows per block.
// ---------------------------------------------------------------------------
#define PP_ROWS 4

__global__ __launch_bounds__(256)
void preproc_kernel(const int* __restrict__ e1_idx,
                    const int* __restrict__ r_idx,
                    const int* __restrict__ t_idx,
                    const float* __restrict__ E,
                    const float* __restrict__ R,
                    const float* __restrict__ T,
                    const float* __restrict__ F0,
                    const float* __restrict__ F1,
                    const float* __restrict__ F3,
                    const float* __restrict__ F2T,
                    float* __restrict__ H)
{
    __shared__ float sE[PP_ROWS][D_SZ];
    __shared__ float sR[PP_ROWS][D_SZ];
    __shared__ float sT[PP_ROWS][D_SZ];
    __shared__ float sG[PP_ROWS][D_SZ];

    const int b0  = blockIdx.x * PP_ROWS;
    const int tid = threadIdx.x;

    for (int r = 0; r < PP_ROWS; r++) {
        const int be = e1_idx[b0 + r];
        const int br = r_idx[b0 + r];
        const int bt = t_idx[b0 + r];
        for (int k = tid; k < D_SZ; k += 256) {
            sE[r][k] = E[(size_t)be * D_SZ + k];
            sR[r][k] = R[(size_t)br * D_SZ + k];
            sT[r][k] = T[(size_t)bt * D_SZ + k];
        }
    }
    __syncthreads();

    // G phase: coalesced along p (lanes -> consecutive p)
    for (int task = tid; task < PP_ROWS * D_SZ; task += 256) {
        const int r = task / D_SZ;
        const int p = task - r * D_SZ;
        float fr = 0.f, fe = 0.f, ft = 0.f;
        #pragma unroll 8
        for (int k = 0; k < D_SZ; k++) {
            fr = fmaf(sR[r][k], F0[k * D_SZ + p], fr);
            fe = fmaf(sE[r][k], F1[k * D_SZ + p], fe);
            ft = fmaf(sT[r][k], F3[k * D_SZ + p], ft);
        }
        sG[r][p] = fr * fe * ft;
    }
    __syncthreads();

    // H phase: coalesced along j (F2T is P-major)
    for (int task = tid; task < PP_ROWS * D_SZ; task += 256) {
        const int r = task / D_SZ;
        const int j = task - r * D_SZ;
        float acc = 0.f;
        const float* g = sG[r];
        #pragma unroll 8
        for (int p = 0; p < D_SZ; p++) {
            acc = fmaf(g[p], F2T[p * D_SZ + j], acc);
        }
        H[(size_t)(b0 + r) * D_SZ + j] = acc;
    }
}

// ---------------------------------------------------------------------------
// Kernel 2: x = sigmoid(H @ E^T),  M=1024, N=100000, K=200, fp32.
// 128x128 block tile, BK=8, 256 threads, 8x8 per thread via fma.rn.f32x2.
//  - A is stored duplicated in smem -> FFMA2 broadcast operand comes straight
//    from LDS.128 (no pack MOVs on the fma pipe).
//  - B fragment is split (tx*4 + h*64) -> LDS.128 at 16B lane stride,
//    conflict degree 2 = the 256B/128B wavefront floor (was 4-way).
// ---------------------------------------------------------------------------
#define BM 128
#define BN 128
#define BK 8
#define KITERS (D_SZ / BK)   // 25

__global__ __launch_bounds__(256, 2)
void gemm_sigmoid_kernel(const float* __restrict__ H,
                         const float* __restrict__ E,
                         float* __restrict__ out)
{
    const int m0 = blockIdx.x * BM;   // 8 m-tiles (fastest-varying -> share E strip in L2)
    const int n0 = blockIdx.y * BN;   // 782 n-tiles

    __shared__ __align__(16) float As[2][BK][BM * 2];  // duplicated: [k][2m]=[k][2m+1]=a
    __shared__ __align__(16) float Bs[2][BK][BN];

    const int tid = threadIdx.x;
    const int tx  = tid & 15;   // n direction (0..15)
    const int ty  = tid >> 4;   // m direction (0..15)

    // global->smem load mapping: thread t loads one float4 of H and one of E
    const int lrow = tid >> 1;          // 0..127
    const int lk   = (tid & 1) * 4;     // 0 or 4

    const float* hptr = H + (size_t)(m0 + lrow) * D_SZ + lk;
    const int    nrow = n0 + lrow;
    const bool   nvalid = (nrow < NE_SZ);
    const float* eptr = E + (size_t)(nvalid ? nrow : 0) * D_SZ + lk;

    unsigned long long acc[8][4];
    #pragma unroll
    for (int i = 0; i < 8; i++)
        #pragma unroll
        for (int j = 0; j < 4; j++) acc[i][j] = 0ull;

    // prologue: load k-chunk 0
    float4 aReg = *reinterpret_cast<const float4*>(hptr);
    float4 bReg = nvalid ? *reinterpret_cast<const float4*>(eptr)
                         : make_float4(0.f, 0.f, 0.f, 0.f);
    {
        float av[4] = {aReg.x, aReg.y, aReg.z, aReg.w};
        float bv[4] = {bReg.x, bReg.y, bReg.z, bReg.w};
        #pragma unroll
        for (int i = 0; i < 4; i++) {
            *reinterpret_cast<float2*>(&As[0][lk + i][2 * lrow]) =
                make_float2(av[i], av[i]);
            Bs[0][lk + i][lrow] = bv[i];
        }
    }
    __syncthreads();

    int buf = 0;
    for (int kt = 0; kt < KITERS; kt++) {
        // prefetch next k-chunk into registers
        if (kt < KITERS - 1) {
            aReg = *reinterpret_cast<const float4*>(hptr + (kt + 1) * BK);
            bReg = nvalid ? *reinterpret_cast<const float4*>(eptr + (kt + 1) * BK)
                          : make_float4(0.f, 0.f, 0.f, 0.f);
        }

        #pragma unroll
        for (int kk = 0; kk < BK; kk++) {
            // A: 8 duplicated values = 4 x LDS.128 (broadcast, 1 wf each)
            const ulonglong2* ap =
                reinterpret_cast<const ulonglong2*>(&As[buf][kk][ty * 16]);
            const ulonglong2 a01 = ap[0];
            const ulonglong2 a23 = ap[1];
            const ulonglong2 a45 = ap[2];
            const ulonglong2 a67 = ap[3];

            // B: two 4-float chunks at tx*4 and 64+tx*4 (conflict-free floor)
            const ulonglong2 b01 =
                *reinterpret_cast<const ulonglong2*>(&Bs[buf][kk][tx * 4]);
            const ulonglong2 b23 =
                *reinterpret_cast<const ulonglong2*>(&Bs[buf][kk][64 + tx * 4]);

            unsigned long long ad[8] = {a01.x, a01.y, a23.x, a23.y,
                                        a45.x, a45.y, a67.x, a67.y};
            #pragma unroll
            for (int i = 0; i < 8; i++) {
                ffma2(acc[i][0], ad[i], b01.x);
                ffma2(acc[i][1], ad[i], b01.y);
                ffma2(acc[i][2], ad[i], b23.x);
                ffma2(acc[i][3], ad[i], b23.y);
            }
        }

        if (kt < KITERS - 1) {
            const int nb = buf ^ 1;
            float av[4] = {aReg.x, aReg.y, aReg.z, aReg.w};
            float bv[4] = {bReg.x, bReg.y, bReg.z, bReg.w};
            #pragma unroll
            for (int i = 0; i < 4; i++) {
                *reinterpret_cast<float2*>(&As[nb][lk + i][2 * lrow]) =
                    make_float2(av[i], av[i]);
                Bs[nb][lk + i][lrow] = bv[i];
            }
            __syncthreads();
            buf = nb;
        }
    }

    // epilogue: sigmoid + store.
    // Thread's columns: n0 + tx*4 + {0..3}  and  n0 + 64 + tx*4 + {0..3}
    #pragma unroll
    for (int i = 0; i < 8; i++) {
        const int m = m0 + ty * 8 + i;           // always < 1024
        float v[8];
        #pragma unroll
        for (int j2 = 0; j2 < 4; j2++) {
            float2 p = unpack2(acc[i][j2]);
            v[2 * j2 + 0] = p.x;
            v[2 * j2 + 1] = p.y;
        }
        #pragma unroll
        for (int j = 0; j < 8; j++)
            v[j] = 1.0f / (1.0f + __expf(-v[j]));

        float* orow = out + (size_t)m * NE_SZ;

        const int nA = n0 + tx * 4;
        if (nA + 4 <= NE_SZ) {
            *reinterpret_cast<float4*>(orow + nA) =
                make_float4(v[0], v[1], v[2], v[3]);
        } else {
            for (int j = 0; j < 4; j++)
                if (nA + j < NE_SZ) orow[nA + j] = v[j];
        }

        const int nB = n0 + 64 + tx * 4;
        if (nB + 4 <= NE_SZ) {
            *reinterpret_cast<float4*>(orow + nB) =
                make_float4(v[4], v[5], v[6], v[7]);
        } else {
            for (int j = 0; j < 4; j++)
                if (nB + j < NE_SZ) orow[nB + j] = v[4 + j];
        }
    }
}

// ---------------------------------------------------------------------------
// Launch. Input order per metadata: e1_idx, r_idx, t_idx, E, R, T, F0, F1, F2, F3
// ---------------------------------------------------------------------------
extern "C" void kernel_launch(void* const* d_in, const int* in_sizes, int n_in,
                              void* d_out, int out_size)
{
    const int*   e1_idx = (const int*)d_in[0];
    const int*   r_idx  = (const int*)d_in[1];
    const int*   t_idx  = (const int*)d_in[2];
    const float* E      = (const float*)d_in[3];
    const float* R      = (const float*)d_in[4];
    const float* T      = (const float*)d_in[5];
    const float* F0     = (const float*)d_in[6];
    const float* F1     = (const float*)d_in[7];
    const float* F2     = (const float*)d_in[8];
    const float* F3     = (const float*)d_in[9];
    float*       out    = (float*)d_out;

    float* H = nullptr;
    float* F2T = nullptr;
    cudaGetSymbolAddress((void**)&H, g_H);
    cudaGetSymbolAddress((void**)&F2T, g_F2T);

    transpose_f2_kernel<<<(D_SZ * D_SZ + 255) / 256, 256>>>(F2, F2T);

    preproc_kernel<<<B_SZ / PP_ROWS, 256>>>(
        e1_idx, r_idx, t_idx, E, R, T, F0, F1, F3, F2T, H);

    dim3 grid(B_SZ / BM, (NE_SZ + BN - 1) / BN);   // (8, 782)
    gemm_sigmoid_kernel<<<grid, 256>>>(H, E, out);
}

// round 6
// speedup vs baseline: 4.7222x; 2.1289x over previous
#include <cuda_runtime.h>
#include <cuda_bf16.h>
#include <cstdint>

// Problem constants
#define B_SZ    1024
#define NE_SZ   100000
#define NE_PAD  100096          // 782 * 128
#define D_SZ    200
#define KPAD    640             // 3*200 = 600 padded to 10*64

// Scratch
__device__ float          g_H[B_SZ * D_SZ];
__device__ float          g_F2T[D_SZ * D_SZ];
__device__ __nv_bfloat16  g_Hcat[B_SZ * KPAD];                 // 1.3 MB
__device__ __nv_bfloat16  g_Ecat[(size_t)NE_PAD * KPAD];       // 128 MB

// ---------------------------------------------------------------------------
// PTX helpers (all baseline PTX: sm_80-class — compiles for plain sm_103)
// ---------------------------------------------------------------------------
__device__ __forceinline__ uint32_t smem_u32(const void* p) {
    uint32_t a;
    asm("{ .reg .u64 t; cvta.to.shared.u64 t, %1; cvt.u32.u64 %0, t; }"
        : "=r"(a) : "l"(p));
    return a;
}

__device__ __forceinline__ void cp_async16(uint32_t dst, const void* src) {
    asm volatile("cp.async.cg.shared.global [%0], [%1], 16;"
                 :: "r"(dst), "l"(src) : "memory");
}

__device__ __forceinline__ void ldsm4(uint32_t& r0, uint32_t& r1,
                                      uint32_t& r2, uint32_t& r3,
                                      uint32_t addr) {
    asm volatile("ldmatrix.sync.aligned.m8n8.x4.shared.b16 {%0,%1,%2,%3}, [%4];"
                 : "=r"(r0), "=r"(r1), "=r"(r2), "=r"(r3) : "r"(addr));
}

__device__ __forceinline__ void mma16816(float* c,
                                         uint32_t a0, uint32_t a1,
                                         uint32_t a2, uint32_t a3,
                                         uint32_t b0, uint32_t b1) {
    asm volatile(
        "mma.sync.aligned.m16n8k16.row.col.f32.bf16.bf16.f32 "
        "{%0,%1,%2,%3}, {%4,%5,%6,%7}, {%8,%9}, {%0,%1,%2,%3};"
        : "+f"(c[0]), "+f"(c[1]), "+f"(c[2]), "+f"(c[3])
        : "r"(a0), "r"(a1), "r"(a2), "r"(a3), "r"(b0), "r"(b1));
}

// ---------------------------------------------------------------------------
// Kernel 0: F2T[p][j] = F2[j][p]
// ---------------------------------------------------------------------------
__global__ __launch_bounds__(256)
void transpose_f2_kernel(const float* __restrict__ F2, float* __restrict__ F2T)
{
    int idx = blockIdx.x * 256 + threadIdx.x;
    if (idx < D_SZ * D_SZ) {
        int p = idx / D_SZ;
        int j = idx - p * D_SZ;
        F2T[idx] = F2[j * D_SZ + p];
    }
}

// ---------------------------------------------------------------------------
// Kernel 1: preprocessing -> H (B x 200), fp32
// ---------------------------------------------------------------------------
#define PP_ROWS 4

__global__ __launch_bounds__(256)
void preproc_kernel(const int* __restrict__ e1_idx,
                    const int* __restrict__ r_idx,
                    const int* __restrict__ t_idx,
                    const float* __restrict__ E,
                    const float* __restrict__ R,
                    const float* __restrict__ T,
                    const float* __restrict__ F0,
                    const float* __restrict__ F1,
                    const float* __restrict__ F3,
                    const float* __restrict__ F2T,
                    float* __restrict__ H)
{
    __shared__ float sE[PP_ROWS][D_SZ];
    __shared__ float sR[PP_ROWS][D_SZ];
    __shared__ float sT[PP_ROWS][D_SZ];
    __shared__ float sG[PP_ROWS][D_SZ];

    const int b0  = blockIdx.x * PP_ROWS;
    const int tid = threadIdx.x;

    for (int r = 0; r < PP_ROWS; r++) {
        const int be = e1_idx[b0 + r];
        const int br = r_idx[b0 + r];
        const int bt = t_idx[b0 + r];
        for (int k = tid; k < D_SZ; k += 256) {
            sE[r][k] = E[(size_t)be * D_SZ + k];
            sR[r][k] = R[(size_t)br * D_SZ + k];
            sT[r][k] = T[(size_t)bt * D_SZ + k];
        }
    }
    __syncthreads();

    for (int task = tid; task < PP_ROWS * D_SZ; task += 256) {
        const int r = task / D_SZ;
        const int p = task - r * D_SZ;
        float fr = 0.f, fe = 0.f, ft = 0.f;
        #pragma unroll 8
        for (int k = 0; k < D_SZ; k++) {
            fr = fmaf(sR[r][k], F0[k * D_SZ + p], fr);
            fe = fmaf(sE[r][k], F1[k * D_SZ + p], fe);
            ft = fmaf(sT[r][k], F3[k * D_SZ + p], ft);
        }
        sG[r][p] = fr * fe * ft;
    }
    __syncthreads();

    for (int task = tid; task < PP_ROWS * D_SZ; task += 256) {
        const int r = task / D_SZ;
        const int j = task - r * D_SZ;
        float acc = 0.f;
        const float* g = sG[r];
        #pragma unroll 8
        for (int p = 0; p < D_SZ; p++)
            acc = fmaf(g[p], F2T[p * D_SZ + j], acc);
        H[(size_t)(b0 + r) * D_SZ + j] = acc;
    }
}

// ---------------------------------------------------------------------------
// Kernel 2: pack into bf16 split-K concat layout (K = 640).
//   Ecat regions along K: [0:200) hi(E), [200:400) lo(E), [400:600) hi(E), pad 0
//   Hcat regions along K: [0:200) hi(H), [200:400) hi(H), [400:600) lo(H), pad 0
// => Hcat·Ecat^T = Hh·Eh + Hh·El + Hl·Eh = H·E − Hl·El  (drop ~2^-16 rel)
// ---------------------------------------------------------------------------
__device__ __forceinline__ void pack8(const float* __restrict__ src,
                                      __nv_bfloat16* __restrict__ dst,
                                      int lo)
{
    float4 x0 = *reinterpret_cast<const float4*>(src);
    float4 x1 = *reinterpret_cast<const float4*>(src + 4);
    float xs[8] = {x0.x, x0.y, x0.z, x0.w, x1.x, x1.y, x1.z, x1.w};
    __nv_bfloat16 o[8];
    #pragma unroll
    for (int j = 0; j < 8; j++) {
        __nv_bfloat16 hi = __float2bfloat16(xs[j]);
        o[j] = lo ? __float2bfloat16(xs[j] - __bfloat162float(hi)) : hi;
    }
    *reinterpret_cast<uint4*>(dst) = *reinterpret_cast<uint4*>(o);
}

__global__ __launch_bounds__(256)
void pack_e_kernel(const float* __restrict__ E, __nv_bfloat16* __restrict__ Ecat)
{
    size_t t = (size_t)blockIdx.x * 256 + threadIdx.x;
    const size_t NT = (size_t)NE_PAD * (KPAD / 8);
    if (t >= NT) return;
    int row = (int)(t / (KPAD / 8));
    int k0  = (int)(t % (KPAD / 8)) * 8;
    __nv_bfloat16* dst = Ecat + (size_t)row * KPAD + k0;
    if (row < NE_SZ && k0 < 600) {
        int region = k0 / 200;                 // 0:hi 1:lo 2:hi
        pack8(E + (size_t)row * D_SZ + (k0 - region * 200), dst, region == 1);
    } else {
        *reinterpret_cast<uint4*>(dst) = make_uint4(0, 0, 0, 0);
    }
}

__global__ __launch_bounds__(256)
void pack_h_kernel(const float* __restrict__ H, __nv_bfloat16* __restrict__ Hcat)
{
    int t = blockIdx.x * 256 + threadIdx.x;
    const int NT = B_SZ * (KPAD / 8);
    if (t >= NT) return;
    int row = t / (KPAD / 8);
    int k0  = (t % (KPAD / 8)) * 8;
    __nv_bfloat16* dst = Hcat + (size_t)row * KPAD + k0;
    if (k0 < 600) {
        int region = k0 / 200;                 // 0:hi 1:hi 2:lo
        pack8(H + (size_t)row * D_SZ + (k0 - region * 200), dst, region == 2);
    } else {
        *reinterpret_cast<uint4*>(dst) = make_uint4(0, 0, 0, 0);
    }
}

// ---------------------------------------------------------------------------
// Kernel 3: x = sigmoid(Hcat @ Ecat^T) via warp-level bf16 mma.sync (HMMA).
// CTA tile 128(M) x 128(N), BK=64 (10 chunks), 256 threads = 8 warps (2m x 4n),
// warp tile 64x32, ldmatrix fragments from XOR-swizzled smem, double-buffered
// cp.async, fp32 accumulators.
// ---------------------------------------------------------------------------
#define KC      64
#define NCHUNK  (KPAD / KC)         // 10
#define CHUNK_BYTES (128 * 128)     // 16 KB per operand (128 rows x 128 B)
#define SMEM_GEMM (4 * CHUNK_BYTES) // 64 KB: A0,A1,B0,B1

__device__ __forceinline__ uint32_t swz(uint32_t off) {
    return off ^ ((off >> 3) & 0x70);
}

// load one 128-row x 128-byte chunk of A and B into smem (swizzled)
__device__ __forceinline__ void load_chunk(uint32_t sA, uint32_t sB,
                                           const __nv_bfloat16* __restrict__ Hc,
                                           const __nv_bfloat16* __restrict__ Ec,
                                           int m0, int n0, int kc, int tid)
{
    const size_t koff = (size_t)kc * KC * 2;
    #pragma unroll
    for (int i = 0; i < 4; i++) {
        int task = tid + i * 256;
        int row = task >> 3, ch = task & 7;
        uint32_t sw = swz(row * 128 + ch * 16);
        cp_async16(sA + sw,
                   (const char*)Hc + ((size_t)(m0 + row) * KPAD) * 2 + koff + ch * 16);
    }
    #pragma unroll
    for (int i = 0; i < 4; i++) {
        int task = tid + i * 256;
        int row = task >> 3, ch = task & 7;
        uint32_t sw = swz(row * 128 + ch * 16);
        cp_async16(sB + sw,
                   (const char*)Ec + ((size_t)(n0 + row) * KPAD) * 2 + koff + ch * 16);
    }
    asm volatile("cp.async.commit_group;" ::: "memory");
}

__global__ __launch_bounds__(256, 2)
void gemm_mma_kernel(const __nv_bfloat16* __restrict__ Hc,
                     const __nv_bfloat16* __restrict__ Ec,
                     float* __restrict__ out)
{
    extern __shared__ char smem[];
    const uint32_t sb = smem_u32(smem);
    const uint32_t sA[2] = {sb,                  sb + CHUNK_BYTES};
    const uint32_t sB[2] = {sb + 2 * CHUNK_BYTES, sb + 3 * CHUNK_BYTES};

    const int tid  = threadIdx.x;
    const int wid  = tid >> 5;
    const int lane = tid & 31;
    const int warp_m = wid & 1;     // 2 warps along M (64 rows each)
    const int warp_n = wid >> 1;    // 4 warps along N (32 cols each)
    const int m0 = blockIdx.x * 128;
    const int n0 = blockIdx.y * 128;

    // ldmatrix lane address components (within-chunk byte offsets)
    // A: matrices [m0..7@k0, m8..15@k0, m0..7@k0+8, m8..15@k0+8]
    uint32_t aRowOff[4], aSwb[4];
    {
        const int rbase = warp_m * 64 + (lane & 15);
        #pragma unroll
        for (int mt = 0; mt < 4; mt++) {
            int row = rbase + mt * 16;
            aRowOff[mt] = row * 128;
            aSwb[mt]    = (row & 7) * 16;
        }
    }
    const uint32_t aKhalf = (lane >> 4) * 16;

    // B: matrices [n0..7@k0, n0..7@k0+8, n8..15@k0, n8..15@k0+8]
    uint32_t bRowOff[2], bSwb[2];
    {
        const int rbase = warp_n * 32 + ((lane >> 4) << 3) + (lane & 7);
        #pragma unroll
        for (int g = 0; g < 2; g++) {
            int row = rbase + g * 16;
            bRowOff[g] = row * 128;
            bSwb[g]    = (row & 7) * 16;
        }
    }
    const uint32_t bKhalf = ((lane >> 3) & 1) * 16;

    float acc[4][4][4];
    #pragma unroll
    for (int mt = 0; mt < 4; mt++)
        #pragma unroll
        for (int nt = 0; nt < 4; nt++)
            #pragma unroll
            for (int r = 0; r < 4; r++) acc[mt][nt][r] = 0.f;

    // prologue
    load_chunk(sA[0], sB[0], Hc, Ec, m0, n0, 0, tid);
    load_chunk(sA[1], sB[1], Hc, Ec, m0, n0, 1, tid);

    for (int kt = 0; kt < NCHUNK; kt++) {
        const int b = kt & 1;
        if (kt < NCHUNK - 1)
            asm volatile("cp.async.wait_group 1;" ::: "memory");
        else
            asm volatile("cp.async.wait_group 0;" ::: "memory");
        __syncthreads();

        #pragma unroll
        for (int ks = 0; ks < 4; ks++) {
            const uint32_t kcol = ks * 32;
            uint32_t a[4][4];
            #pragma unroll
            for (int mt = 0; mt < 4; mt++)
                ldsm4(a[mt][0], a[mt][1], a[mt][2], a[mt][3],
                      sA[b] + aRowOff[mt] + ((kcol + aKhalf) ^ aSwb[mt]));
            uint32_t bb[2][4];
            #pragma unroll
            for (int g = 0; g < 2; g++)
                ldsm4(bb[g][0], bb[g][1], bb[g][2], bb[g][3],
                      sB[b] + bRowOff[g] + ((kcol + bKhalf) ^ bSwb[g]));

            #pragma unroll
            for (int mt = 0; mt < 4; mt++)
                #pragma unroll
                for (int nt = 0; nt < 4; nt++)
                    mma16816(acc[mt][nt],
                             a[mt][0], a[mt][1], a[mt][2], a[mt][3],
                             bb[nt >> 1][(nt & 1) * 2],
                             bb[nt >> 1][(nt & 1) * 2 + 1]);
        }

        if (kt <= NCHUNK - 3) {
            __syncthreads();   // all warps done reading buf b
            load_chunk(sA[b], sB[b], Hc, Ec, m0, n0, kt + 2, tid);
        }
    }

    // epilogue: sigmoid + store (float2 per fragment half; NE_SZ even, n even)
    const int mBase = m0 + warp_m * 64 + (lane >> 2);
    const int nBase = n0 + warp_n * 32 + (lane & 3) * 2;
    #pragma unroll
    for (int mt = 0; mt < 4; mt++) {
        #pragma unroll
        for (int nt = 0; nt < 4; nt++) {
            const int n = nBase + nt * 8;
            if (n < NE_SZ) {
                const int m = mBase + mt * 16;
                float2 v0, v1;
                v0.x = 1.f / (1.f + __expf(-acc[mt][nt][0]));
                v0.y = 1.f / (1.f + __expf(-acc[mt][nt][1]));
                v1.x = 1.f / (1.f + __expf(-acc[mt][nt][2]));
                v1.y = 1.f / (1.f + __expf(-acc[mt][nt][3]));
                *reinterpret_cast<float2*>(out + (size_t)m * NE_SZ + n)       = v0;
                *reinterpret_cast<float2*>(out + (size_t)(m + 8) * NE_SZ + n) = v1;
            }
        }
    }
}

// ---------------------------------------------------------------------------
// Launch. Inputs: e1_idx, r_idx, t_idx, E, R, T, F0, F1, F2, F3
// ---------------------------------------------------------------------------
extern "C" void kernel_launch(void* const* d_in, const int* in_sizes, int n_in,
                              void* d_out, int out_size)
{
    const int*   e1_idx = (const int*)d_in[0];
    const int*   r_idx  = (const int*)d_in[1];
    const int*   t_idx  = (const int*)d_in[2];
    const float* E      = (const float*)d_in[3];
    const float* R      = (const float*)d_in[4];
    const float* T      = (const float*)d_in[5];
    const float* F0     = (const float*)d_in[6];
    const float* F1     = (const float*)d_in[7];
    const float* F2     = (const float*)d_in[8];
    const float* F3     = (const float*)d_in[9];
    float*       out    = (float*)d_out;

    float *H, *F2T;
    __nv_bfloat16 *Hcat, *Ecat;
    cudaGetSymbolAddress((void**)&H,    g_H);
    cudaGetSymbolAddress((void**)&F2T,  g_F2T);
    cudaGetSymbolAddress((void**)&Hcat, g_Hcat);
    cudaGetSymbolAddress((void**)&Ecat, g_Ecat);

    static bool attr_set = false;
    if (!attr_set) {
        cudaFuncSetAttribute(gemm_mma_kernel,
                             cudaFuncAttributeMaxDynamicSharedMemorySize,
                             SMEM_GEMM);
        attr_set = true;
    }

    transpose_f2_kernel<<<(D_SZ * D_SZ + 255) / 256, 256>>>(F2, F2T);

    preproc_kernel<<<B_SZ / PP_ROWS, 256>>>(
        e1_idx, r_idx, t_idx, E, R, T, F0, F1, F3, F2T, H);

    pack_h_kernel<<<(B_SZ * (KPAD / 8) + 255) / 256, 256>>>(H, Hcat);

    {
        size_t nt = (size_t)NE_PAD * (KPAD / 8);
        pack_e_kernel<<<(unsigned)((nt + 255) / 256), 256>>>(E, Ecat);
    }

    dim3 grid(B_SZ / 128, NE_PAD / 128);   // (8, 782), m fastest
    gemm_mma_kernel<<<grid, 256, SMEM_GEMM>>>(Hcat, Ecat, out);
}

// round 7
// speedup vs baseline: 5.4747x; 1.1594x over previous
#include <cuda_runtime.h>
#include <cuda_fp16.h>
#include <cstdint>

// Problem constants
#define B_SZ    1024
#define NE_SZ   100000
#define NE_PAD  100096          // 782 * 128
#define D_SZ    200
#define KPAD    448             // 2*200 = 400 padded to 7*64

// Scratch
__device__ float   g_H[B_SZ * D_SZ];
__device__ float   g_F2T[D_SZ * D_SZ];
__device__ __half  g_Hcat[B_SZ * KPAD];                 // 0.92 MB
__device__ __half  g_Ecat[(size_t)NE_PAD * KPAD];       // 89.7 MB

// ---------------------------------------------------------------------------
// PTX helpers (baseline sm_80-class PTX — compiles for plain sm_103)
// ---------------------------------------------------------------------------
__device__ __forceinline__ uint32_t smem_u32(const void* p) {
    uint32_t a;
    asm("{ .reg .u64 t; cvta.to.shared.u64 t, %1; cvt.u32.u64 %0, t; }"
        : "=r"(a) : "l"(p));
    return a;
}

__device__ __forceinline__ void cp_async16(uint32_t dst, const void* src) {
    asm volatile("cp.async.cg.shared.global [%0], [%1], 16;"
                 :: "r"(dst), "l"(src) : "memory");
}

__device__ __forceinline__ void ldsm4(uint32_t& r0, uint32_t& r1,
                                      uint32_t& r2, uint32_t& r3,
                                      uint32_t addr) {
    asm volatile("ldmatrix.sync.aligned.m8n8.x4.shared.b16 {%0,%1,%2,%3}, [%4];"
                 : "=r"(r0), "=r"(r1), "=r"(r2), "=r"(r3) : "r"(addr));
}

__device__ __forceinline__ void mma16816(float* c,
                                         uint32_t a0, uint32_t a1,
                                         uint32_t a2, uint32_t a3,
                                         uint32_t b0, uint32_t b1) {
    asm volatile(
        "mma.sync.aligned.m16n8k16.row.col.f32.f16.f16.f32 "
        "{%0,%1,%2,%3}, {%4,%5,%6,%7}, {%8,%9}, {%0,%1,%2,%3};"
        : "+f"(c[0]), "+f"(c[1]), "+f"(c[2]), "+f"(c[3])
        : "r"(a0), "r"(a1), "r"(a2), "r"(a3), "r"(b0), "r"(b1));
}

// ---------------------------------------------------------------------------
// Kernel 0: F2T[p][j] = F2[j][p]
// ---------------------------------------------------------------------------
__global__ __launch_bounds__(256)
void transpose_f2_kernel(const float* __restrict__ F2, float* __restrict__ F2T)
{
    int idx = blockIdx.x * 256 + threadIdx.x;
    if (idx < D_SZ * D_SZ) {
        int p = idx / D_SZ;
        int j = idx - p * D_SZ;
        F2T[idx] = F2[j * D_SZ + p];
    }
}

// ---------------------------------------------------------------------------
// Kernel 1: preprocessing -> H (B x 200), fp32
// ---------------------------------------------------------------------------
#define PP_ROWS 4

__global__ __launch_bounds__(256)
void preproc_kernel(const int* __restrict__ e1_idx,
                    const int* __restrict__ r_idx,
                    const int* __restrict__ t_idx,
                    const float* __restrict__ E,
                    const float* __restrict__ R,
                    const float* __restrict__ T,
                    const float* __restrict__ F0,
                    const float* __restrict__ F1,
                    const float* __restrict__ F3,
                    const float* __restrict__ F2T,
                    float* __restrict__ H)
{
    __shared__ float sE[PP_ROWS][D_SZ];
    __shared__ float sR[PP_ROWS][D_SZ];
    __shared__ float sT[PP_ROWS][D_SZ];
    __shared__ float sG[PP_ROWS][D_SZ];

    const int b0  = blockIdx.x * PP_ROWS;
    const int tid = threadIdx.x;

    for (int r = 0; r < PP_ROWS; r++) {
        const int be = e1_idx[b0 + r];
        const int br = r_idx[b0 + r];
        const int bt = t_idx[b0 + r];
        for (int k = tid; k < D_SZ; k += 256) {
            sE[r][k] = E[(size_t)be * D_SZ + k];
            sR[r][k] = R[(size_t)br * D_SZ + k];
            sT[r][k] = T[(size_t)bt * D_SZ + k];
        }
    }
    __syncthreads();

    for (int task = tid; task < PP_ROWS * D_SZ; task += 256) {
        const int r = task / D_SZ;
        const int p = task - r * D_SZ;
        float fr = 0.f, fe = 0.f, ft = 0.f;
        #pragma unroll 8
        for (int k = 0; k < D_SZ; k++) {
            fr = fmaf(sR[r][k], F0[k * D_SZ + p], fr);
            fe = fmaf(sE[r][k], F1[k * D_SZ + p], fe);
            ft = fmaf(sT[r][k], F3[k * D_SZ + p], ft);
        }
        sG[r][p] = fr * fe * ft;
    }
    __syncthreads();

    for (int task = tid; task < PP_ROWS * D_SZ; task += 256) {
        const int r = task / D_SZ;
        const int j = task - r * D_SZ;
        float acc = 0.f;
        const float* g = sG[r];
        #pragma unroll 8
        for (int p = 0; p < D_SZ; p++)
            acc = fmaf(g[p], F2T[p * D_SZ + j], acc);
        H[(size_t)(b0 + r) * D_SZ + j] = acc;
    }
}

// ---------------------------------------------------------------------------
// Kernel 2: pack into fp16 2-term split-K layout (K = 448).
//   Ecat regions along K: [0:200) hi(E), [200:400) lo(E), pad 0
//   Hcat regions along K: [0:200) hi(H), [200:400) hi(H), pad 0
// => Hcat·Ecat^T = Hh·Eh + Hh·El = Hh·E ;  error = Hl·E ~ 2^-12 rel
// ---------------------------------------------------------------------------
__device__ __forceinline__ void pack8h(const float* __restrict__ src,
                                       __half* __restrict__ dst,
                                       int lo)
{
    float4 x0 = *reinterpret_cast<const float4*>(src);
    float4 x1 = *reinterpret_cast<const float4*>(src + 4);
    float xs[8] = {x0.x, x0.y, x0.z, x0.w, x1.x, x1.y, x1.z, x1.w};
    __half o[8];
    #pragma unroll
    for (int j = 0; j < 8; j++) {
        __half hi = __float2half_rn(xs[j]);
        o[j] = lo ? __float2half_rn(xs[j] - __half2float(hi)) : hi;
    }
    *reinterpret_cast<uint4*>(dst) = *reinterpret_cast<uint4*>(o);
}

__global__ __launch_bounds__(256)
void pack_e_kernel(const float* __restrict__ E, __half* __restrict__ Ecat)
{
    size_t t = (size_t)blockIdx.x * 256 + threadIdx.x;
    const size_t NT = (size_t)NE_PAD * (KPAD / 8);
    if (t >= NT) return;
    int row = (int)(t / (KPAD / 8));
    int k0  = (int)(t % (KPAD / 8)) * 8;
    __half* dst = Ecat + (size_t)row * KPAD + k0;
    if (row < NE_SZ && k0 < 400) {
        int region = k0 / 200;                 // 0:hi 1:lo
        pack8h(E + (size_t)row * D_SZ + (k0 - region * 200), dst, region == 1);
    } else {
        *reinterpret_cast<uint4*>(dst) = make_uint4(0, 0, 0, 0);
    }
}

__global__ __launch_bounds__(256)
void pack_h_kernel(const float* __restrict__ H, __half* __restrict__ Hcat)
{
    int t = blockIdx.x * 256 + threadIdx.x;
    const int NT = B_SZ * (KPAD / 8);
    if (t >= NT) return;
    int row = t / (KPAD / 8);
    int k0  = (t % (KPAD / 8)) * 8;
    __half* dst = Hcat + (size_t)row * KPAD + k0;
    if (k0 < 400) {
        int region = k0 / 200;                 // 0:hi 1:hi
        pack8h(H + (size_t)row * D_SZ + (k0 - region * 200), dst, 0);
    } else {
        *reinterpret_cast<uint4*>(dst) = make_uint4(0, 0, 0, 0);
    }
}

// ---------------------------------------------------------------------------
// Kernel 3: x = sigmoid(Hcat @ Ecat^T) via warp-level fp16 mma.sync.
// CTA tile 256(M) x 128(N), BK=64 (7 chunks), 512 threads = 16 warps (4m x 4n),
// warp tile 64x32 (identical fragment mapping to the proven R6 kernel).
// 3-stage cp.async pipeline, one __syncthreads per chunk.
// ---------------------------------------------------------------------------
#define BM      256
#define BN      128
#define NCHUNK  (KPAD / 64)         // 7
#define ACHUNK  (BM * 128)          // 32 KB
#define BCHUNK  (BN * 128)          // 16 KB
#define STAGE_BYTES (ACHUNK + BCHUNK)
#define SMEM_GEMM (3 * STAGE_BYTES) // 144 KB

__device__ __forceinline__ uint32_t swz(uint32_t off) {
    return off ^ ((off >> 3) & 0x70);
}

__device__ __forceinline__ void load_chunk(uint32_t sA, uint32_t sB,
                                           const __half* __restrict__ Hc,
                                           const __half* __restrict__ Ec,
                                           int m0, int n0, int kc, int tid)
{
    const size_t koff = (size_t)kc * 128;   // 64 cols * 2B
    #pragma unroll
    for (int i = 0; i < 4; i++) {           // A: 256 rows x 128B
        int task = tid + i * 512;
        int row = task >> 3, ch = task & 7;
        cp_async16(sA + swz(row * 128 + ch * 16),
                   (const char*)Hc + ((size_t)(m0 + row) * KPAD) * 2 + koff + ch * 16);
    }
    #pragma unroll
    for (int i = 0; i < 2; i++) {           // B: 128 rows x 128B
        int task = tid + i * 512;
        int row = task >> 3, ch = task & 7;
        cp_async16(sB + swz(row * 128 + ch * 16),
                   (const char*)Ec + ((size_t)(n0 + row) * KPAD) * 2 + koff + ch * 16);
    }
    asm volatile("cp.async.commit_group;" ::: "memory");
}

__global__ __launch_bounds__(512, 1)
void gemm_mma_kernel(const __half* __restrict__ Hc,
                     const __half* __restrict__ Ec,
                     float* __restrict__ out)
{
    extern __shared__ char smem[];
    const uint32_t sb = smem_u32(smem);
    uint32_t sA[3], sB[3];
    #pragma unroll
    for (int s = 0; s < 3; s++) {
        sA[s] = sb + s * STAGE_BYTES;
        sB[s] = sA[s] + ACHUNK;
    }

    const int tid  = threadIdx.x;
    const int wid  = tid >> 5;
    const int lane = tid & 31;
    const int warp_m = wid & 3;     // 4 warps along M (64 rows each)
    const int warp_n = wid >> 2;    // 4 warps along N (32 cols each)
    const int m0 = blockIdx.x * BM; // 4 m-tiles, fastest -> share Ecat strip in L2
    const int n0 = blockIdx.y * BN;

    // A fragment addressing (within-chunk byte offsets)
    uint32_t aRowOff[4], aSwb[4];
    {
        const int rbase = warp_m * 64 + (lane & 15);
        #pragma unroll
        for (int mt = 0; mt < 4; mt++) {
            int row = rbase + mt * 16;
            aRowOff[mt] = row * 128;
            aSwb[mt]    = (row & 7) * 16;
        }
    }
    const uint32_t aKhalf = (lane >> 4) * 16;

    // B fragment addressing
    uint32_t bRowOff[2], bSwb[2];
    {
        const int rbase = warp_n * 32 + ((lane >> 4) << 3) + (lane & 7);
        #pragma unroll
        for (int g = 0; g < 2; g++) {
            int row = rbase + g * 16;
            bRowOff[g] = row * 128;
            bSwb[g]    = (row & 7) * 16;
        }
    }
    const uint32_t bKhalf = ((lane >> 3) & 1) * 16;

    float acc[4][4][4];
    #pragma unroll
    for (int mt = 0; mt < 4; mt++)
        #pragma unroll
        for (int nt = 0; nt < 4; nt++)
            #pragma unroll
            for (int r = 0; r < 4; r++) acc[mt][nt][r] = 0.f;

    // prologue: stages 0,1
    load_chunk(sA[0], sB[0], Hc, Ec, m0, n0, 0, tid);
    load_chunk(sA[1], sB[1], Hc, Ec, m0, n0, 1, tid);

    for (int kt = 0; kt < NCHUNK; kt++) {
        const int s = kt % 3;
        if (kt < NCHUNK - 1)
            asm volatile("cp.async.wait_group 1;" ::: "memory");
        else
            asm volatile("cp.async.wait_group 0;" ::: "memory");
        __syncthreads();

        if (kt + 2 < NCHUNK)
            load_chunk(sA[(kt + 2) % 3], sB[(kt + 2) % 3],
                       Hc, Ec, m0, n0, kt + 2, tid);

        #pragma unroll
        for (int ks = 0; ks < 4; ks++) {
            const uint32_t kcol = ks * 32;
            uint32_t a[4][4];
            #pragma unroll
            for (int mt = 0; mt < 4; mt++)
                ldsm4(a[mt][0], a[mt][1], a[mt][2], a[mt][3],
                      sA[s] + aRowOff[mt] + ((kcol + aKhalf) ^ aSwb[mt]));
            uint32_t bb[2][4];
            #pragma unroll
            for (int g = 0; g < 2; g++)
                ldsm4(bb[g][0], bb[g][1], bb[g][2], bb[g][3],
                      sB[s] + bRowOff[g] + ((kcol + bKhalf) ^ bSwb[g]));

            #pragma unroll
            for (int mt = 0; mt < 4; mt++)
                #pragma unroll
                for (int nt = 0; nt < 4; nt++)
                    mma16816(acc[mt][nt],
                             a[mt][0], a[mt][1], a[mt][2], a[mt][3],
                             bb[nt >> 1][(nt & 1) * 2],
                             bb[nt >> 1][(nt & 1) * 2 + 1]);
        }
    }

    // epilogue: sigmoid + store (float2 halves; NE_SZ even, n even)
    const int mBase = m0 + warp_m * 64 + (lane >> 2);
    const int nBase = n0 + warp_n * 32 + (lane & 3) * 2;
    #pragma unroll
    for (int mt = 0; mt < 4; mt++) {
        #pragma unroll
        for (int nt = 0; nt < 4; nt++) {
            const int n = nBase + nt * 8;
            if (n < NE_SZ) {
                const int m = mBase + mt * 16;
                float2 v0, v1;
                v0.x = 1.f / (1.f + __expf(-acc[mt][nt][0]));
                v0.y = 1.f / (1.f + __expf(-acc[mt][nt][1]));
                v1.x = 1.f / (1.f + __expf(-acc[mt][nt][2]));
                v1.y = 1.f / (1.f + __expf(-acc[mt][nt][3]));
                *reinterpret_cast<float2*>(out + (size_t)m * NE_SZ + n)       = v0;
                *reinterpret_cast<float2*>(out + (size_t)(m + 8) * NE_SZ + n) = v1;
            }
        }
    }
}

// ---------------------------------------------------------------------------
// Launch. Inputs: e1_idx, r_idx, t_idx, E, R, T, F0, F1, F2, F3
// ---------------------------------------------------------------------------
extern "C" void kernel_launch(void* const* d_in, const int* in_sizes, int n_in,
                              void* d_out, int out_size)
{
    const int*   e1_idx = (const int*)d_in[0];
    const int*   r_idx  = (const int*)d_in[1];
    const int*   t_idx  = (const int*)d_in[2];
    const float* E      = (const float*)d_in[3];
    const float* R      = (const float*)d_in[4];
    const float* T      = (const float*)d_in[5];
    const float* F0     = (const float*)d_in[6];
    const float* F1     = (const float*)d_in[7];
    const float* F2     = (const float*)d_in[8];
    const float* F3     = (const float*)d_in[9];
    float*       out    = (float*)d_out;

    float *H, *F2T;
    __half *Hcat, *Ecat;
    cudaGetSymbolAddress((void**)&H,    g_H);
    cudaGetSymbolAddress((void**)&F2T,  g_F2T);
    cudaGetSymbolAddress((void**)&Hcat, g_Hcat);
    cudaGetSymbolAddress((void**)&Ecat, g_Ecat);

    static bool attr_set = false;
    if (!attr_set) {
        cudaFuncSetAttribute(gemm_mma_kernel,
                             cudaFuncAttributeMaxDynamicSharedMemorySize,
                             SMEM_GEMM);
        attr_set = true;
    }

    transpose_f2_kernel<<<(D_SZ * D_SZ + 255) / 256, 256>>>(F2, F2T);

    preproc_kernel<<<B_SZ / PP_ROWS, 256>>>(
        e1_idx, r_idx, t_idx, E, R, T, F0, F1, F3, F2T, H);

    pack_h_kernel<<<(B_SZ * (KPAD / 8) + 255) / 256, 256>>>(H, Hcat);

    {
        size_t nt = (size_t)NE_PAD * (KPAD / 8);
        pack_e_kernel<<<(unsigned)((nt + 255) / 256), 256>>>(E, Ecat);
    }

    dim3 grid(B_SZ / BM, NE_PAD / BN);   // (4, 782), m fastest
    gemm_mma_kernel<<<grid, 512, SMEM_GEMM>>>(Hcat, Ecat, out);
}

// round 8
// speedup vs baseline: 7.2728x; 1.3284x over previous
#include <cuda_runtime.h>
#include <cuda_fp16.h>
#include <cstdint>

// Problem constants
#define B_SZ    1024
#define NE_SZ   100000
#define NE_PAD  100096          // 782 * 128
#define D_SZ    200
#define KPAD    256             // 200 (fp16 hi only) padded to 4*64

// Scratch
__device__ float   g_H[B_SZ * D_SZ];
__device__ float   g_F2T[D_SZ * D_SZ];
__device__ __half  g_Hcat[B_SZ * KPAD];                 // 0.5 MB
__device__ __half  g_Ecat[(size_t)NE_PAD * KPAD];       // 51.2 MB

// ---------------------------------------------------------------------------
// PTX helpers (baseline sm_80-class PTX — compiles for plain sm_103)
// ---------------------------------------------------------------------------
__device__ __forceinline__ uint32_t smem_u32(const void* p) {
    uint32_t a;
    asm("{ .reg .u64 t; cvta.to.shared.u64 t, %1; cvt.u32.u64 %0, t; }"
        : "=r"(a) : "l"(p));
    return a;
}

__device__ __forceinline__ void cp_async16(uint32_t dst, const void* src) {
    asm volatile("cp.async.cg.shared.global [%0], [%1], 16;"
                 :: "r"(dst), "l"(src) : "memory");
}

__device__ __forceinline__ void ldsm4(uint32_t& r0, uint32_t& r1,
                                      uint32_t& r2, uint32_t& r3,
                                      uint32_t addr) {
    asm volatile("ldmatrix.sync.aligned.m8n8.x4.shared.b16 {%0,%1,%2,%3}, [%4];"
                 : "=r"(r0), "=r"(r1), "=r"(r2), "=r"(r3) : "r"(addr));
}

__device__ __forceinline__ void mma16816(float* c,
                                         uint32_t a0, uint32_t a1,
                                         uint32_t a2, uint32_t a3,
                                         uint32_t b0, uint32_t b1) {
    asm volatile(
        "mma.sync.aligned.m16n8k16.row.col.f32.f16.f16.f32 "
        "{%0,%1,%2,%3}, {%4,%5,%6,%7}, {%8,%9}, {%0,%1,%2,%3};"
        : "+f"(c[0]), "+f"(c[1]), "+f"(c[2]), "+f"(c[3])
        : "r"(a0), "r"(a1), "r"(a2), "r"(a3), "r"(b0), "r"(b1));
}

// ---------------------------------------------------------------------------
// Kernel 0: F2T[p][j] = F2[j][p]
// ---------------------------------------------------------------------------
__global__ __launch_bounds__(256)
void transpose_f2_kernel(const float* __restrict__ F2, float* __restrict__ F2T)
{
    int idx = blockIdx.x * 256 + threadIdx.x;
    if (idx < D_SZ * D_SZ) {
        int p = idx / D_SZ;
        int j = idx - p * D_SZ;
        F2T[idx] = F2[j * D_SZ + p];
    }
}

// ---------------------------------------------------------------------------
// Kernel 1: preprocessing -> H (B x 200), fp32
// ---------------------------------------------------------------------------
#define PP_ROWS 4

__global__ __launch_bounds__(256)
void preproc_kernel(const int* __restrict__ e1_idx,
                    const int* __restrict__ r_idx,
                    const int* __restrict__ t_idx,
                    const float* __restrict__ E,
                    const float* __restrict__ R,
                    const float* __restrict__ T,
                    const float* __restrict__ F0,
                    const float* __restrict__ F1,
                    const float* __restrict__ F3,
                    const float* __restrict__ F2T,
                    float* __restrict__ H)
{
    __shared__ float sE[PP_ROWS][D_SZ];
    __shared__ float sR[PP_ROWS][D_SZ];
    __shared__ float sT[PP_ROWS][D_SZ];
    __shared__ float sG[PP_ROWS][D_SZ];

    const int b0  = blockIdx.x * PP_ROWS;
    const int tid = threadIdx.x;

    for (int r = 0; r < PP_ROWS; r++) {
        const int be = e1_idx[b0 + r];
        const int br = r_idx[b0 + r];
        const int bt = t_idx[b0 + r];
        for (int k = tid; k < D_SZ; k += 256) {
            sE[r][k] = E[(size_t)be * D_SZ + k];
            sR[r][k] = R[(size_t)br * D_SZ + k];
            sT[r][k] = T[(size_t)bt * D_SZ + k];
        }
    }
    __syncthreads();

    for (int task = tid; task < PP_ROWS * D_SZ; task += 256) {
        const int r = task / D_SZ;
        const int p = task - r * D_SZ;
        float fr = 0.f, fe = 0.f, ft = 0.f;
        #pragma unroll 8
        for (int k = 0; k < D_SZ; k++) {
            fr = fmaf(sR[r][k], F0[k * D_SZ + p], fr);
            fe = fmaf(sE[r][k], F1[k * D_SZ + p], fe);
            ft = fmaf(sT[r][k], F3[k * D_SZ + p], ft);
        }
        sG[r][p] = fr * fe * ft;
    }
    __syncthreads();

    for (int task = tid; task < PP_ROWS * D_SZ; task += 256) {
        const int r = task / D_SZ;
        const int j = task - r * D_SZ;
        float acc = 0.f;
        const float* g = sG[r];
        #pragma unroll 8
        for (int p = 0; p < D_SZ; p++)
            acc = fmaf(g[p], F2T[p * D_SZ + j], acc);
        H[(size_t)(b0 + r) * D_SZ + j] = acc;
    }
}

// ---------------------------------------------------------------------------
// Kernel 2: pack hi(fp16) of H and E, K padded 200 -> 256.
// Product Hh·Eh ; error = Hl·E + Hh·El ~ 2^-11.8 rel (calibrated vs R7).
// ---------------------------------------------------------------------------
__device__ __forceinline__ void pack8h(const float* __restrict__ src,
                                       __half* __restrict__ dst)
{
    float4 x0 = *reinterpret_cast<const float4*>(src);
    float4 x1 = *reinterpret_cast<const float4*>(src + 4);
    float xs[8] = {x0.x, x0.y, x0.z, x0.w, x1.x, x1.y, x1.z, x1.w};
    __half o[8];
    #pragma unroll
    for (int j = 0; j < 8; j++) o[j] = __float2half_rn(xs[j]);
    *reinterpret_cast<uint4*>(dst) = *reinterpret_cast<uint4*>(o);
}

__global__ __launch_bounds__(256)
void pack_e_kernel(const float* __restrict__ E, __half* __restrict__ Ecat)
{
    size_t t = (size_t)blockIdx.x * 256 + threadIdx.x;
    const size_t NT = (size_t)NE_PAD * (KPAD / 8);
    if (t >= NT) return;
    int row = (int)(t / (KPAD / 8));
    int k0  = (int)(t % (KPAD / 8)) * 8;
    __half* dst = Ecat + (size_t)row * KPAD + k0;
    if (row < NE_SZ && k0 < D_SZ)
        pack8h(E + (size_t)row * D_SZ + k0, dst);
    else
        *reinterpret_cast<uint4*>(dst) = make_uint4(0, 0, 0, 0);
}

__global__ __launch_bounds__(256)
void pack_h_kernel(const float* __restrict__ H, __half* __restrict__ Hcat)
{
    int t = blockIdx.x * 256 + threadIdx.x;
    const int NT = B_SZ * (KPAD / 8);
    if (t >= NT) return;
    int row = t / (KPAD / 8);
    int k0  = (t % (KPAD / 8)) * 8;
    __half* dst = Hcat + (size_t)row * KPAD + k0;
    if (k0 < D_SZ)
        pack8h(H + (size_t)row * D_SZ + k0, dst);
    else
        *reinterpret_cast<uint4*>(dst) = make_uint4(0, 0, 0, 0);
}

// ---------------------------------------------------------------------------
// Kernel 3: x = sigmoid(Hcat @ Ecat^T) via warp-level fp16 mma.sync.
// CTA tile 128x128, BK=64 (4 chunks), 256 threads = 8 warps (2m x 4n),
// warp tile 64x32 (R6-proven fragment mapping), 3-stage cp.async pipeline,
// one __syncthreads per chunk, occupancy 2.
// ---------------------------------------------------------------------------
#define BM      128
#define BN      128
#define NCHUNK  (KPAD / 64)         // 4
#define ACHUNK  (BM * 128)          // 16 KB
#define BCHUNK  (BN * 128)          // 16 KB
#define STAGE_BYTES (ACHUNK + BCHUNK)
#define SMEM_GEMM (3 * STAGE_BYTES) // 96 KB -> 2 CTAs/SM

__device__ __forceinline__ uint32_t swz(uint32_t off) {
    return off ^ ((off >> 3) & 0x70);
}

__device__ __forceinline__ void load_chunk(uint32_t sA, uint32_t sB,
                                           const __half* __restrict__ Hc,
                                           const __half* __restrict__ Ec,
                                           int m0, int n0, int kc, int tid)
{
    const size_t koff = (size_t)kc * 128;   // 64 cols * 2B
    #pragma unroll
    for (int i = 0; i < 4; i++) {           // A: 128 rows x 128B
        int task = tid + i * 256;
        int row = task >> 3, ch = task & 7;
        cp_async16(sA + swz(row * 128 + ch * 16),
                   (const char*)Hc + ((size_t)(m0 + row) * KPAD) * 2 + koff + ch * 16);
    }
    #pragma unroll
    for (int i = 0; i < 4; i++) {           // B: 128 rows x 128B
        int task = tid + i * 256;
        int row = task >> 3, ch = task & 7;
        cp_async16(sB + swz(row * 128 + ch * 16),
                   (const char*)Ec + ((size_t)(n0 + row) * KPAD) * 2 + koff + ch * 16);
    }
    asm volatile("cp.async.commit_group;" ::: "memory");
}

__global__ __launch_bounds__(256, 2)
void gemm_mma_kernel(const __half* __restrict__ Hc,
                     const __half* __restrict__ Ec,
                     float* __restrict__ out)
{
    extern __shared__ char smem[];
    const uint32_t sb = smem_u32(smem);
    uint32_t sA[3], sB[3];
    #pragma unroll
    for (int s = 0; s < 3; s++) {
        sA[s] = sb + s * STAGE_BYTES;
        sB[s] = sA[s] + ACHUNK;
    }

    const int tid  = threadIdx.x;
    const int wid  = tid >> 5;
    const int lane = tid & 31;
    const int warp_m = wid & 1;     // 2 warps along M (64 rows each)
    const int warp_n = wid >> 1;    // 4 warps along N (32 cols each)
    const int m0 = blockIdx.x * BM; // 8 m-tiles, fastest -> share Ecat strip in L2
    const int n0 = blockIdx.y * BN;

    // A fragment addressing (within-chunk byte offsets) — R6-proven mapping
    uint32_t aRowOff[4], aSwb[4];
    {
        const int rbase = warp_m * 64 + (lane & 15);
        #pragma unroll
        for (int mt = 0; mt < 4; mt++) {
            int row = rbase + mt * 16;
            aRowOff[mt] = row * 128;
            aSwb[mt]    = (row & 7) * 16;
        }
    }
    const uint32_t aKhalf = (lane >> 4) * 16;

    // B fragment addressing
    uint32_t bRowOff[2], bSwb[2];
    {
        const int rbase = warp_n * 32 + ((lane >> 4) << 3) + (lane & 7);
        #pragma unroll
        for (int g = 0; g < 2; g++) {
            int row = rbase + g * 16;
            bRowOff[g] = row * 128;
            bSwb[g]    = (row & 7) * 16;
        }
    }
    const uint32_t bKhalf = ((lane >> 3) & 1) * 16;

    float acc[4][4][4];
    #pragma unroll
    for (int mt = 0; mt < 4; mt++)
        #pragma unroll
        for (int nt = 0; nt < 4; nt++)
            #pragma unroll
            for (int r = 0; r < 4; r++) acc[mt][nt][r] = 0.f;

    // prologue: stages 0,1
    load_chunk(sA[0], sB[0], Hc, Ec, m0, n0, 0, tid);
    load_chunk(sA[1], sB[1], Hc, Ec, m0, n0, 1, tid);

    for (int kt = 0; kt < NCHUNK; kt++) {
        const int s = kt % 3;
        if (kt < NCHUNK - 1)
            asm volatile("cp.async.wait_group 1;" ::: "memory");
        else
            asm volatile("cp.async.wait_group 0;" ::: "memory");
        __syncthreads();

        if (kt + 2 < NCHUNK)
            load_chunk(sA[(kt + 2) % 3], sB[(kt + 2) % 3],
                       Hc, Ec, m0, n0, kt + 2, tid);

        #pragma unroll
        for (int ks = 0; ks < 4; ks++) {
            const uint32_t kcol = ks * 32;
            uint32_t a[4][4];
            #pragma unroll
            for (int mt = 0; mt < 4; mt++)
                ldsm4(a[mt][0], a[mt][1], a[mt][2], a[mt][3],
                      sA[s] + aRowOff[mt] + ((kcol + aKhalf) ^ aSwb[mt]));
            uint32_t bb[2][4];
            #pragma unroll
            for (int g = 0; g < 2; g++)
                ldsm4(bb[g][0], bb[g][1], bb[g][2], bb[g][3],
                      sB[s] + bRowOff[g] + ((kcol + bKhalf) ^ bSwb[g]));

            #pragma unroll
            for (int mt = 0; mt < 4; mt++)
                #pragma unroll
                for (int nt = 0; nt < 4; nt++)
                    mma16816(acc[mt][nt],
                             a[mt][0], a[mt][1], a[mt][2], a[mt][3],
                             bb[nt >> 1][(nt & 1) * 2],
                             bb[nt >> 1][(nt & 1) * 2 + 1]);
        }
    }

    // epilogue: sigmoid + store (float2 halves; NE_SZ even, n even)
    const int mBase = m0 + warp_m * 64 + (lane >> 2);
    const int nBase = n0 + warp_n * 32 + (lane & 3) * 2;
    #pragma unroll
    for (int mt = 0; mt < 4; mt++) {
        #pragma unroll
        for (int nt = 0; nt < 4; nt++) {
            const int n = nBase + nt * 8;
            if (n < NE_SZ) {
                const int m = mBase + mt * 16;
                float2 v0, v1;
                v0.x = 1.f / (1.f + __expf(-acc[mt][nt][0]));
                v0.y = 1.f / (1.f + __expf(-acc[mt][nt][1]));
                v1.x = 1.f / (1.f + __expf(-acc[mt][nt][2]));
                v1.y = 1.f / (1.f + __expf(-acc[mt][nt][3]));
                *reinterpret_cast<float2*>(out + (size_t)m * NE_SZ + n)       = v0;
                *reinterpret_cast<float2*>(out + (size_t)(m + 8) * NE_SZ + n) = v1;
            }
        }
    }
}

// ---------------------------------------------------------------------------
// Launch. Inputs: e1_idx, r_idx, t_idx, E, R, T, F0, F1, F2, F3
// ---------------------------------------------------------------------------
extern "C" void kernel_launch(void* const* d_in, const int* in_sizes, int n_in,
                              void* d_out, int out_size)
{
    const int*   e1_idx = (const int*)d_in[0];
    const int*   r_idx  = (const int*)d_in[1];
    const int*   t_idx  = (const int*)d_in[2];
    const float* E      = (const float*)d_in[3];
    const float* R      = (const float*)d_in[4];
    const float* T      = (const float*)d_in[5];
    const float* F0     = (const float*)d_in[6];
    const float* F1     = (const float*)d_in[7];
    const float* F2     = (const float*)d_in[8];
    const float* F3     = (const float*)d_in[9];
    float*       out    = (float*)d_out;

    float *H, *F2T;
    __half *Hcat, *Ecat;
    cudaGetSymbolAddress((void**)&H,    g_H);
    cudaGetSymbolAddress((void**)&F2T,  g_F2T);
    cudaGetSymbolAddress((void**)&Hcat, g_Hcat);
    cudaGetSymbolAddress((void**)&Ecat, g_Ecat);

    static bool attr_set = false;
    if (!attr_set) {
        cudaFuncSetAttribute(gemm_mma_kernel,
                             cudaFuncAttributeMaxDynamicSharedMemorySize,
                             SMEM_GEMM);
        attr_set = true;
    }

    transpose_f2_kernel<<<(D_SZ * D_SZ + 255) / 256, 256>>>(F2, F2T);

    preproc_kernel<<<B_SZ / PP_ROWS, 256>>>(
        e1_idx, r_idx, t_idx, E, R, T, F0, F1, F3, F2T, H);

    pack_h_kernel<<<(B_SZ * (KPAD / 8) + 255) / 256, 256>>>(H, Hcat);

    {
        size_t nt = (size_t)NE_PAD * (KPAD / 8);
        pack_e_kernel<<<(unsigned)((nt + 255) / 256), 256>>>(E, Ecat);
    }

    dim3 grid(B_SZ / BM, NE_PAD / BN);   // (8, 782), m fastest
    gemm_mma_kernel<<<grid, 256, SMEM_GEMM>>>(Hcat, Ecat, out);
}

// round 9
// speedup vs baseline: 7.3679x; 1.0131x over previous
#include <cuda_runtime.h>
#include <cuda_fp16.h>
#include <cstdint>

// Problem constants
#define B_SZ    1024
#define NE_SZ   100000
#define NE_PAD  100096          // 782 * 128
#define NTILES  782
#define D_SZ    200
#define KPAD    256             // row stride of packed operands (bytes/2)
#define KUSE    208             // 200 real + 8 zero (partial 4th chunk)

// Scratch
__device__ float   g_F2T[D_SZ * D_SZ];
__device__ __half  g_Hcat[B_SZ * KPAD];                 // 0.5 MB (pad cols stay 0)
__device__ __half  g_Ecat[(size_t)NE_PAD * KPAD];       // 51.2 MB

// ---------------------------------------------------------------------------
// PTX helpers (baseline sm_80-class PTX — compiles for plain sm_103)
// ---------------------------------------------------------------------------
__device__ __forceinline__ uint32_t smem_u32(const void* p) {
    uint32_t a;
    asm("{ .reg .u64 t; cvta.to.shared.u64 t, %1; cvt.u32.u64 %0, t; }"
        : "=r"(a) : "l"(p));
    return a;
}

__device__ __forceinline__ void cp_async16(uint32_t dst, const void* src) {
    asm volatile("cp.async.cg.shared.global [%0], [%1], 16;"
                 :: "r"(dst), "l"(src) : "memory");
}

__device__ __forceinline__ void ldsm4(uint32_t& r0, uint32_t& r1,
                                      uint32_t& r2, uint32_t& r3,
                                      uint32_t addr) {
    asm volatile("ldmatrix.sync.aligned.m8n8.x4.shared.b16 {%0,%1,%2,%3}, [%4];"
                 : "=r"(r0), "=r"(r1), "=r"(r2), "=r"(r3) : "r"(addr));
}

__device__ __forceinline__ void mma16816(float* c,
                                         uint32_t a0, uint32_t a1,
                                         uint32_t a2, uint32_t a3,
                                         uint32_t b0, uint32_t b1) {
    asm volatile(
        "mma.sync.aligned.m16n8k16.row.col.f32.f16.f16.f32 "
        "{%0,%1,%2,%3}, {%4,%5,%6,%7}, {%8,%9}, {%0,%1,%2,%3};"
        : "+f"(c[0]), "+f"(c[1]), "+f"(c[2]), "+f"(c[3])
        : "r"(a0), "r"(a1), "r"(a2), "r"(a3), "r"(b0), "r"(b1));
}

__device__ __forceinline__ uint32_t swz(uint32_t off) {
    return off ^ ((off >> 3) & 0x70);
}

// ---------------------------------------------------------------------------
// Kernel 0: F2T[p][j] = F2[j][p]
// ---------------------------------------------------------------------------
__global__ __launch_bounds__(256)
void transpose_f2_kernel(const float* __restrict__ F2, float* __restrict__ F2T)
{
    int idx = blockIdx.x * 256 + threadIdx.x;
    if (idx < D_SZ * D_SZ) {
        int p = idx / D_SZ;
        int j = idx - p * D_SZ;
        F2T[idx] = F2[j * D_SZ + p];
    }
}

// ---------------------------------------------------------------------------
// Kernel 1: preprocessing -> Hcat (fp16, cols 0..199; pad cols stay zero-init)
//   G[b][p] = (R[r]F0)[p] * (E[e1]F1)[p] * (T[t]F3)[p]
//   Hcat[b][j] = fp16( sum_p G[b][p] * F2T[p][j] )
// ---------------------------------------------------------------------------
#define PP_ROWS 4

__global__ __launch_bounds__(256)
void preproc_kernel(const int* __restrict__ e1_idx,
                    const int* __restrict__ r_idx,
                    const int* __restrict__ t_idx,
                    const float* __restrict__ E,
                    const float* __restrict__ R,
                    const float* __restrict__ T,
                    const float* __restrict__ F0,
                    const float* __restrict__ F1,
                    const float* __restrict__ F3,
                    const float* __restrict__ F2T,
                    __half* __restrict__ Hcat)
{
    __shared__ float sE[PP_ROWS][D_SZ];
    __shared__ float sR[PP_ROWS][D_SZ];
    __shared__ float sT[PP_ROWS][D_SZ];
    __shared__ float sG[PP_ROWS][D_SZ];

    const int b0  = blockIdx.x * PP_ROWS;
    const int tid = threadIdx.x;

    for (int r = 0; r < PP_ROWS; r++) {
        const int be = e1_idx[b0 + r];
        const int br = r_idx[b0 + r];
        const int bt = t_idx[b0 + r];
        for (int k = tid; k < D_SZ; k += 256) {
            sE[r][k] = E[(size_t)be * D_SZ + k];
            sR[r][k] = R[(size_t)br * D_SZ + k];
            sT[r][k] = T[(size_t)bt * D_SZ + k];
        }
    }
    __syncthreads();

    for (int task = tid; task < PP_ROWS * D_SZ; task += 256) {
        const int r = task / D_SZ;
        const int p = task - r * D_SZ;
        float fr = 0.f, fe = 0.f, ft = 0.f;
        #pragma unroll 8
        for (int k = 0; k < D_SZ; k++) {
            fr = fmaf(sR[r][k], F0[k * D_SZ + p], fr);
            fe = fmaf(sE[r][k], F1[k * D_SZ + p], fe);
            ft = fmaf(sT[r][k], F3[k * D_SZ + p], ft);
        }
        sG[r][p] = fr * fe * ft;
    }
    __syncthreads();

    for (int task = tid; task < PP_ROWS * D_SZ; task += 256) {
        const int r = task / D_SZ;
        const int j = task - r * D_SZ;
        float acc = 0.f;
        const float* g = sG[r];
        #pragma unroll 8
        for (int p = 0; p < D_SZ; p++)
            acc = fmaf(g[p], F2T[p * D_SZ + j], acc);
        Hcat[(size_t)(b0 + r) * KPAD + j] = __float2half_rn(acc);
    }
}

// ---------------------------------------------------------------------------
// Kernel 2: pack hi(fp16) of E into Ecat; only cols [0,208) are ever read.
// Rows >= NE and cols [200,208) are zeros.
// ---------------------------------------------------------------------------
#define KCH 26   // 208/8 column-chunks per row

__global__ __launch_bounds__(256)
void pack_e_kernel(const float* __restrict__ E, __half* __restrict__ Ecat)
{
    size_t t = (size_t)blockIdx.x * 256 + threadIdx.x;
    const size_t NT = (size_t)NE_PAD * KCH;
    if (t >= NT) return;
    int row = (int)(t / KCH);
    int k0  = (int)(t % KCH) * 8;
    __half* dst = Ecat + (size_t)row * KPAD + k0;
    if (row < NE_SZ && k0 < D_SZ) {
        float4 x0 = *reinterpret_cast<const float4*>(E + (size_t)row * D_SZ + k0);
        float4 x1 = *reinterpret_cast<const float4*>(E + (size_t)row * D_SZ + k0 + 4);
        __half o[8] = {
            __float2half_rn(x0.x), __float2half_rn(x0.y),
            __float2half_rn(x0.z), __float2half_rn(x0.w),
            __float2half_rn(x1.x), __float2half_rn(x1.y),
            __float2half_rn(x1.z), __float2half_rn(x1.w)};
        *reinterpret_cast<uint4*>(dst) = *reinterpret_cast<uint4*>(o);
    } else {
        *reinterpret_cast<uint4*>(dst) = make_uint4(0, 0, 0, 0);
    }
}

// ---------------------------------------------------------------------------
// Kernel 3: x = sigmoid(Hcat @ Ecat^T), warp-level fp16 mma.sync.
// A-resident persistent-n: CTA = 128 M-rows; A (128 x 256, 64 KB) loaded once;
// NTPC=4 n-tiles of 128 streamed through a 3-stage B ring (3 x 16 KB).
// K effective = 208: chunks 0..2 full (64 cols), chunk 3 partial (16 cols).
// 256 threads = 8 warps (2m x 4n), warp tile 64x32 (R6-proven mapping), occ 2.
// ---------------------------------------------------------------------------
#define NTPC     4
#define NGRP     196                 // ceil(782/4); tiles >781 clamp to 781
#define A_BYTES  (4 * 16384)         // 64 KB (4 chunks of 128x64)
#define B_STAGE  16384               // 16 KB per B stage
#define SMEM_GEMM (A_BYTES + 3 * B_STAGE)   // 112 KB -> 2 CTAs/SM

__device__ __forceinline__ void load_B(uint32_t sB,
                                       const __half* __restrict__ Ec,
                                       int n0, int kt, int tid)
{
    const char* base = (const char*)Ec + (size_t)n0 * (KPAD * 2) + kt * 128;
    if (kt < 3) {
        #pragma unroll
        for (int i = 0; i < 4; i++) {          // 128 rows x 8 chunks
            int task = tid + i * 256;
            int row = task >> 3, ch = task & 7;
            cp_async16(sB + swz(row * 128 + ch * 16),
                       base + (size_t)row * (KPAD * 2) + ch * 16);
        }
    } else {                                   // partial: 128 rows x 2 chunks
        int row = tid >> 1, ch = tid & 1;
        cp_async16(sB + swz(row * 128 + ch * 16),
                   base + (size_t)row * (KPAD * 2) + ch * 16);
    }
    asm volatile("cp.async.commit_group;" ::: "memory");
}

__global__ __launch_bounds__(256, 2)
void gemm_mma_kernel(const __half* __restrict__ Hc,
                     const __half* __restrict__ Ec,
                     float* __restrict__ out)
{
    extern __shared__ char smem[];
    const uint32_t sb     = smem_u32(smem);
    const uint32_t sAbase = sb;
    const uint32_t sBbase = sb + A_BYTES;

    const int tid  = threadIdx.x;
    const int wid  = tid >> 5;
    const int lane = tid & 31;
    const int warp_m = wid & 1;
    const int warp_n = wid >> 1;
    const int m0 = blockIdx.x * 128;       // 8 m-CTAs fastest -> share B strip in L2
    const int gy = blockIdx.y;             // 196 n-groups of NTPC tiles

    // ---- A resident load: 4096 x 16B, one group ----
    #pragma unroll
    for (int i = 0; i < 16; i++) {
        int task = tid + i * 256;
        int ktc = task >> 10;
        int r   = (task >> 3) & 127;
        int ch  = task & 7;
        cp_async16(sAbase + ktc * 16384 + swz(r * 128 + ch * 16),
                   (const char*)Hc + (size_t)(m0 + r) * (KPAD * 2) + ktc * 128 + ch * 16);
    }
    asm volatile("cp.async.commit_group;" ::: "memory");

    // ---- B prologue: chunks 0, 1 ----
    {
        int nt0 = gy * NTPC;           if (nt0 > NTILES - 1) nt0 = NTILES - 1;
        load_B(sBbase + (0 % 3) * B_STAGE, Ec, nt0 * 128, 0, tid);
        load_B(sBbase + (1 % 3) * B_STAGE, Ec, nt0 * 128, 1, tid);
    }

    // fragment addressing (within-chunk byte offsets) — R6-proven mapping
    uint32_t aRowOff[4], aSwb[4];
    {
        const int rbase = warp_m * 64 + (lane & 15);
        #pragma unroll
        for (int mt = 0; mt < 4; mt++) {
            int row = rbase + mt * 16;
            aRowOff[mt] = row * 128;
            aSwb[mt]    = (row & 7) * 16;
        }
    }
    const uint32_t aKhalf = (lane >> 4) * 16;

    uint32_t bRowOff[2], bSwb[2];
    {
        const int rbase = warp_n * 32 + ((lane >> 4) << 3) + (lane & 7);
        #pragma unroll
        for (int g = 0; g < 2; g++) {
            int row = rbase + g * 16;
            bRowOff[g] = row * 128;
            bSwb[g]    = (row & 7) * 16;
        }
    }
    const uint32_t bKhalf = ((lane >> 3) & 1) * 16;

    float acc[4][4][4];
    #pragma unroll
    for (int mt = 0; mt < 4; mt++)
        #pragma unroll
        for (int nt = 0; nt < 4; nt++)
            #pragma unroll
            for (int r = 0; r < 4; r++) acc[mt][nt][r] = 0.f;

    const int mBase = m0 + warp_m * 64 + (lane >> 2);
    const int nOff  = warp_n * 32 + (lane & 3) * 2;

    #pragma unroll 1
    for (int tile = 0; tile < NTPC; tile++) {
        #pragma unroll
        for (int kt = 0; kt < 4; kt++) {
            const int c = tile * 4 + kt;

            if (c < NTPC * 4 - 1)
                asm volatile("cp.async.wait_group 1;" ::: "memory");
            else
                asm volatile("cp.async.wait_group 0;" ::: "memory");
            __syncthreads();

            if (c + 2 < NTPC * 4) {
                const int c2 = c + 2;
                int nt2 = gy * NTPC + (c2 >> 2);
                if (nt2 > NTILES - 1) nt2 = NTILES - 1;
                load_B(sBbase + (c2 % 3) * B_STAGE, Ec, nt2 * 128, c2 & 3, tid);
            }

            const uint32_t sAc = sAbase + kt * 16384;
            const uint32_t sBc = sBbase + (c % 3) * B_STAGE;
            const int nks = (kt < 3) ? 4 : 1;   // partial chunk: 16 cols only

            #pragma unroll
            for (int ks = 0; ks < nks; ks++) {
                const uint32_t kcol = ks * 32;
                uint32_t a[4][4];
                #pragma unroll
                for (int mt = 0; mt < 4; mt++)
                    ldsm4(a[mt][0], a[mt][1], a[mt][2], a[mt][3],
                          sAc + aRowOff[mt] + ((kcol + aKhalf) ^ aSwb[mt]));
                uint32_t bb[2][4];
                #pragma unroll
                for (int g = 0; g < 2; g++)
                    ldsm4(bb[g][0], bb[g][1], bb[g][2], bb[g][3],
                          sBc + bRowOff[g] + ((kcol + bKhalf) ^ bSwb[g]));

                #pragma unroll
                for (int mt = 0; mt < 4; mt++)
                    #pragma unroll
                    for (int nt = 0; nt < 4; nt++)
                        mma16816(acc[mt][nt],
                                 a[mt][0], a[mt][1], a[mt][2], a[mt][3],
                                 bb[nt >> 1][(nt & 1) * 2],
                                 bb[nt >> 1][(nt & 1) * 2 + 1]);
            }
        }

        // ---- epilogue for this tile (overlaps in-flight B loads of next) ----
        {
            int ntile = gy * NTPC + tile;
            if (ntile > NTILES - 1) ntile = NTILES - 1;
            const int n0 = ntile * 128;
            #pragma unroll
            for (int mt = 0; mt < 4; mt++) {
                #pragma unroll
                for (int nt = 0; nt < 4; nt++) {
                    const int n = n0 + nOff + nt * 8;
                    if (n < NE_SZ) {
                        const int m = mBase + mt * 16;
                        float2 v0, v1;
                        v0.x = 1.f / (1.f + __expf(-acc[mt][nt][0]));
                        v0.y = 1.f / (1.f + __expf(-acc[mt][nt][1]));
                        v1.x = 1.f / (1.f + __expf(-acc[mt][nt][2]));
                        v1.y = 1.f / (1.f + __expf(-acc[mt][nt][3]));
                        *reinterpret_cast<float2*>(out + (size_t)m * NE_SZ + n)       = v0;
                        *reinterpret_cast<float2*>(out + (size_t)(m + 8) * NE_SZ + n) = v1;
                    }
                    #pragma unroll
                    for (int r = 0; r < 4; r++) acc[mt][nt][r] = 0.f;
                }
            }
        }
    }
}

// ---------------------------------------------------------------------------
// Launch. Inputs: e1_idx, r_idx, t_idx, E, R, T, F0, F1, F2, F3
// ---------------------------------------------------------------------------
extern "C" void kernel_launch(void* const* d_in, const int* in_sizes, int n_in,
                              void* d_out, int out_size)
{
    const int*   e1_idx = (const int*)d_in[0];
    const int*   r_idx  = (const int*)d_in[1];
    const int*   t_idx  = (const int*)d_in[2];
    const float* E      = (const float*)d_in[3];
    const float* R      = (const float*)d_in[4];
    const float* T      = (const float*)d_in[5];
    const float* F0     = (const float*)d_in[6];
    const float* F1     = (const float*)d_in[7];
    const float* F2     = (const float*)d_in[8];
    const float* F3     = (const float*)d_in[9];
    float*       out    = (float*)d_out;

    float* F2T;
    __half *Hcat, *Ecat;
    cudaGetSymbolAddress((void**)&F2T,  g_F2T);
    cudaGetSymbolAddress((void**)&Hcat, g_Hcat);
    cudaGetSymbolAddress((void**)&Ecat, g_Ecat);

    static bool attr_set = false;
    if (!attr_set) {
        cudaFuncSetAttribute(gemm_mma_kernel,
                             cudaFuncAttributeMaxDynamicSharedMemorySize,
                             SMEM_GEMM);
        attr_set = true;
    }

    transpose_f2_kernel<<<(D_SZ * D_SZ + 255) / 256, 256>>>(F2, F2T);

    preproc_kernel<<<B_SZ / PP_ROWS, 256>>>(
        e1_idx, r_idx, t_idx, E, R, T, F0, F1, F3, F2T, Hcat);

    {
        size_t nt = (size_t)NE_PAD * KCH;
        pack_e_kernel<<<(unsigned)((nt + 255) / 256), 256>>>(E, Ecat);
    }

    dim3 grid(B_SZ / 128, NGRP);   // (8, 196), m fastest
    gemm_mma_kernel<<<grid, 256, SMEM_GEMM>>>(Hcat, Ecat, out);
}

// round 10
// speedup vs baseline: 8.1760x; 1.1097x over previous
#include <cuda_runtime.h>
#include <cuda_fp16.h>
#include <cstdint>

// Problem constants
#define B_SZ    1024
#define NE_SZ   100000
#define NE_PAD  100096          // 782 * 128
#define NTILES  782
#define D_SZ    200
#define KPAD    256             // row stride of packed operands (elements)

// Scratch
__device__ float   g_F2T[D_SZ * D_SZ];
__device__ __half  g_Hcat[B_SZ * KPAD];                 // 0.5 MB (pad cols stay 0)
__device__ __half  g_Ecat[(size_t)NE_PAD * KPAD];       // 51.2 MB

// ---------------------------------------------------------------------------
// PTX helpers (baseline sm_80-class PTX — compiles for plain sm_103)
// ---------------------------------------------------------------------------
__device__ __forceinline__ uint32_t smem_u32(const void* p) {
    uint32_t a;
    asm("{ .reg .u64 t; cvta.to.shared.u64 t, %1; cvt.u32.u64 %0, t; }"
        : "=r"(a) : "l"(p));
    return a;
}

__device__ __forceinline__ void cp_async16(uint32_t dst, const void* src) {
    asm volatile("cp.async.cg.shared.global [%0], [%1], 16;"
                 :: "r"(dst), "l"(src) : "memory");
}

__device__ __forceinline__ void ldsm4(uint32_t& r0, uint32_t& r1,
                                      uint32_t& r2, uint32_t& r3,
                                      uint32_t addr) {
    asm volatile("ldmatrix.sync.aligned.m8n8.x4.shared.b16 {%0,%1,%2,%3}, [%4];"
                 : "=r"(r0), "=r"(r1), "=r"(r2), "=r"(r3) : "r"(addr));
}

__device__ __forceinline__ void mma16816(float* c,
                                         uint32_t a0, uint32_t a1,
                                         uint32_t a2, uint32_t a3,
                                         uint32_t b0, uint32_t b1) {
    asm volatile(
        "mma.sync.aligned.m16n8k16.row.col.f32.f16.f16.f32 "
        "{%0,%1,%2,%3}, {%4,%5,%6,%7}, {%8,%9}, {%0,%1,%2,%3};"
        : "+f"(c[0]), "+f"(c[1]), "+f"(c[2]), "+f"(c[3])
        : "r"(a0), "r"(a1), "r"(a2), "r"(a3), "r"(b0), "r"(b1));
}

__device__ __forceinline__ uint32_t swz(uint32_t off) {
    return off ^ ((off >> 3) & 0x70);
}

// sigmoid(x) = 0.5*tanh(0.5x) + 0.5 : 1 MUFU + 2 fma-pipe ops (was 2 MUFU)
__device__ __forceinline__ float fast_sigmoid(float x) {
    float t;
    asm("tanh.approx.f32 %0, %1;" : "=f"(t) : "f"(x * 0.5f));
    return fmaf(0.5f, t, 0.5f);
}

// ---------------------------------------------------------------------------
// Kernel 0: F2T[p][j] = F2[j][p]
// ---------------------------------------------------------------------------
__global__ __launch_bounds__(256)
void transpose_f2_kernel(const float* __restrict__ F2, float* __restrict__ F2T)
{
    int idx = blockIdx.x * 256 + threadIdx.x;
    if (idx < D_SZ * D_SZ) {
        int p = idx / D_SZ;
        int j = idx - p * D_SZ;
        F2T[idx] = F2[j * D_SZ + p];
    }
}

// ---------------------------------------------------------------------------
// Kernel 1: preprocessing -> Hcat (fp16, cols 0..199; pad cols stay zero-init)
// ---------------------------------------------------------------------------
#define PP_ROWS 4

__global__ __launch_bounds__(256)
void preproc_kernel(const int* __restrict__ e1_idx,
                    const int* __restrict__ r_idx,
                    const int* __restrict__ t_idx,
                    const float* __restrict__ E,
                    const float* __restrict__ R,
                    const float* __restrict__ T,
                    const float* __restrict__ F0,
                    const float* __restrict__ F1,
                    const float* __restrict__ F3,
                    const float* __restrict__ F2T,
                    __half* __restrict__ Hcat)
{
    __shared__ float sE[PP_ROWS][D_SZ];
    __shared__ float sR[PP_ROWS][D_SZ];
    __shared__ float sT[PP_ROWS][D_SZ];
    __shared__ float sG[PP_ROWS][D_SZ];

    const int b0  = blockIdx.x * PP_ROWS;
    const int tid = threadIdx.x;

    for (int r = 0; r < PP_ROWS; r++) {
        const int be = e1_idx[b0 + r];
        const int br = r_idx[b0 + r];
        const int bt = t_idx[b0 + r];
        for (int k = tid; k < D_SZ; k += 256) {
            sE[r][k] = E[(size_t)be * D_SZ + k];
            sR[r][k] = R[(size_t)br * D_SZ + k];
            sT[r][k] = T[(size_t)bt * D_SZ + k];
        }
    }
    __syncthreads();

    for (int task = tid; task < PP_ROWS * D_SZ; task += 256) {
        const int r = task / D_SZ;
        const int p = task - r * D_SZ;
        float fr = 0.f, fe = 0.f, ft = 0.f;
        #pragma unroll 8
        for (int k = 0; k < D_SZ; k++) {
            fr = fmaf(sR[r][k], F0[k * D_SZ + p], fr);
            fe = fmaf(sE[r][k], F1[k * D_SZ + p], fe);
            ft = fmaf(sT[r][k], F3[k * D_SZ + p], ft);
        }
        sG[r][p] = fr * fe * ft;
    }
    __syncthreads();

    for (int task = tid; task < PP_ROWS * D_SZ; task += 256) {
        const int r = task / D_SZ;
        const int j = task - r * D_SZ;
        float acc = 0.f;
        const float* g = sG[r];
        #pragma unroll 8
        for (int p = 0; p < D_SZ; p++)
            acc = fmaf(g[p], F2T[p * D_SZ + j], acc);
        Hcat[(size_t)(b0 + r) * KPAD + j] = __float2half_rn(acc);
    }
}

// ---------------------------------------------------------------------------
// Kernel 2: pack hi(fp16) of E into Ecat; cols [0,208) are read by the GEMM.
// ---------------------------------------------------------------------------
#define KCH 26   // 208/8 column-chunks per row

__global__ __launch_bounds__(256)
void pack_e_kernel(const float* __restrict__ E, __half* __restrict__ Ecat)
{
    size_t t = (size_t)blockIdx.x * 256 + threadIdx.x;
    const size_t NT = (size_t)NE_PAD * KCH;
    if (t >= NT) return;
    int row = (int)(t / KCH);
    int k0  = (int)(t % KCH) * 8;
    __half* dst = Ecat + (size_t)row * KPAD + k0;
    if (row < NE_SZ && k0 < D_SZ) {
        float4 x0 = *reinterpret_cast<const float4*>(E + (size_t)row * D_SZ + k0);
        float4 x1 = *reinterpret_cast<const float4*>(E + (size_t)row * D_SZ + k0 + 4);
        __half o[8] = {
            __float2half_rn(x0.x), __float2half_rn(x0.y),
            __float2half_rn(x0.z), __float2half_rn(x0.w),
            __float2half_rn(x1.x), __float2half_rn(x1.y),
            __float2half_rn(x1.z), __float2half_rn(x1.w)};
        *reinterpret_cast<uint4*>(dst) = *reinterpret_cast<uint4*>(o);
    } else {
        *reinterpret_cast<uint4*>(dst) = make_uint4(0, 0, 0, 0);
    }
}

// ---------------------------------------------------------------------------
// Kernel 3: x = sigmoid(Hcat @ Ecat^T), warp-level fp16 mma.sync.
// A-resident persistent-n: 128 M-rows resident (52 KB staged of a 64 KB buf);
// NTPC=8 n-tiles through a 3-stage B ring. K eff = 208 (3 full + 1/4 chunk).
// 256 threads = 8 warps (2m x 4n), warp tile 64x32, occ 2.
// B fragments double-buffered; sigmoid via tanh.approx (1 MUFU).
// ---------------------------------------------------------------------------
#define NTPC     8
#define NGRP     98                  // 98*8 = 784 tiles >= 782 (clamp dups)
#define A_BYTES  (4 * 16384)         // buffer for 4 chunks (4th partially used)
#define B_STAGE  16384
#define SMEM_GEMM (A_BYTES + 3 * B_STAGE)   // 112 KB -> 2 CTAs/SM

__device__ __forceinline__ void load_B(uint32_t sB,
                                       const __half* __restrict__ Ec,
                                       int n0, int kt, int tid)
{
    const char* base = (const char*)Ec + (size_t)n0 * (KPAD * 2) + kt * 128;
    if (kt < 3) {
        #pragma unroll
        for (int i = 0; i < 4; i++) {          // 128 rows x 8 chunks
            int task = tid + i * 256;
            int row = task >> 3, ch = task & 7;
            cp_async16(sB + swz(row * 128 + ch * 16),
                       base + (size_t)row * (KPAD * 2) + ch * 16);
        }
    } else {                                   // partial: 128 rows x 2 chunks
        int row = tid >> 1, ch = tid & 1;
        cp_async16(sB + swz(row * 128 + ch * 16),
                   base + (size_t)row * (KPAD * 2) + ch * 16);
    }
    asm volatile("cp.async.commit_group;" ::: "memory");
}

__global__ __launch_bounds__(256, 2)
void gemm_mma_kernel(const __half* __restrict__ Hc,
                     const __half* __restrict__ Ec,
                     float* __restrict__ out)
{
    extern __shared__ char smem[];
    const uint32_t sb     = smem_u32(smem);
    const uint32_t sAbase = sb;
    const uint32_t sBbase = sb + A_BYTES;

    const int tid  = threadIdx.x;
    const int wid  = tid >> 5;
    const int lane = tid & 31;
    const int warp_m = wid & 1;
    const int warp_n = wid >> 1;
    const int m0 = blockIdx.x * 128;       // 8 m-CTAs fastest -> share B strip in L2
    const int gy = blockIdx.y;             // 98 n-groups of NTPC tiles

    // ---- A resident load: chunks 0-2 full + chunk 3 slots {0,1} (52 KB) ----
    #pragma unroll
    for (int i = 0; i < 13; i++) {
        int task = tid + i * 256;          // 0..3327
        int ktc, r, ch;
        if (task < 3072) { ktc = task >> 10; r = (task >> 3) & 127; ch = task & 7; }
        else             { int t2 = task - 3072; ktc = 3; r = t2 >> 1; ch = t2 & 1; }
        cp_async16(sAbase + ktc * 16384 + swz(r * 128 + ch * 16),
                   (const char*)Hc + (size_t)(m0 + r) * (KPAD * 2) + ktc * 128 + ch * 16);
    }
    asm volatile("cp.async.commit_group;" ::: "memory");

    // ---- B prologue: chunks 0, 1 of first tile ----
    {
        int nt0 = gy * NTPC;           if (nt0 > NTILES - 1) nt0 = NTILES - 1;
        load_B(sBbase + 0 * B_STAGE, Ec, nt0 * 128, 0, tid);
        load_B(sBbase + 1 * B_STAGE, Ec, nt0 * 128, 1, tid);
    }

    // fragment addressing (within-chunk byte offsets)
    uint32_t aRowOff[4], aSwb[4];
    {
        const int rbase = warp_m * 64 + (lane & 15);
        #pragma unroll
        for (int mt = 0; mt < 4; mt++) {
            int row = rbase + mt * 16;
            aRowOff[mt] = row * 128;
            aSwb[mt]    = (row & 7) * 16;
        }
    }
    const uint32_t aKhalf = (lane >> 4) * 16;

    uint32_t bRowOff[2], bSwb[2];
    {
        const int rbase = warp_n * 32 + ((lane >> 4) << 3) + (lane & 7);
        #pragma unroll
        for (int g = 0; g < 2; g++) {
            int row = rbase + g * 16;
            bRowOff[g] = row * 128;
            bSwb[g]    = (row & 7) * 16;
        }
    }
    const uint32_t bKhalf = ((lane >> 3) & 1) * 16;

    float acc[4][4][4];
    #pragma unroll
    for (int mt = 0; mt < 4; mt++)
        #pragma unroll
        for (int nt = 0; nt < 4; nt++)
            #pragma unroll
            for (int r = 0; r < 4; r++) acc[mt][nt][r] = 0.f;

    const int mBase = m0 + warp_m * 64 + (lane >> 2);
    const int nOff  = warp_n * 32 + (lane & 3) * 2;

    #pragma unroll 1
    for (int tile = 0; tile < NTPC; tile++) {
        #pragma unroll
        for (int kt = 0; kt < 4; kt++) {
            const int c = tile * 4 + kt;

            if (c < NTPC * 4 - 1)
                asm volatile("cp.async.wait_group 1;" ::: "memory");
            else
                asm volatile("cp.async.wait_group 0;" ::: "memory");
            __syncthreads();

            if (c + 2 < NTPC * 4) {
                const int c2 = c + 2;
                int nt2 = gy * NTPC + (c2 >> 2);
                if (nt2 > NTILES - 1) nt2 = NTILES - 1;
                load_B(sBbase + (c2 % 3) * B_STAGE, Ec, nt2 * 128, c2 & 3, tid);
            }

            const uint32_t sAc = sAbase + kt * 16384;
            const uint32_t sBc = sBbase + (c % 3) * B_STAGE;
            const int nks = (kt < 3) ? 4 : 1;   // partial chunk: k16 only

            // B fragments double-buffered across ks steps
            uint32_t bbuf[2][2][4];
            #pragma unroll
            for (int g = 0; g < 2; g++)
                ldsm4(bbuf[0][g][0], bbuf[0][g][1], bbuf[0][g][2], bbuf[0][g][3],
                      sBc + bRowOff[g] + (bKhalf ^ bSwb[g]));

            #pragma unroll
            for (int ks = 0; ks < nks; ks++) {
                if (ks + 1 < nks) {
                    const uint32_t kcn = (ks + 1) * 32;
                    #pragma unroll
                    for (int g = 0; g < 2; g++)
                        ldsm4(bbuf[(ks + 1) & 1][g][0], bbuf[(ks + 1) & 1][g][1],
                              bbuf[(ks + 1) & 1][g][2], bbuf[(ks + 1) & 1][g][3],
                              sBc + bRowOff[g] + ((kcn + bKhalf) ^ bSwb[g]));
                }

                const uint32_t kcol = ks * 32;
                uint32_t a[4][4];
                #pragma unroll
                for (int mt = 0; mt < 4; mt++)
                    ldsm4(a[mt][0], a[mt][1], a[mt][2], a[mt][3],
                          sAc + aRowOff[mt] + ((kcol + aKhalf) ^ aSwb[mt]));

                const int pb = ks & 1;
                #pragma unroll
                for (int mt = 0; mt < 4; mt++)
                    #pragma unroll
                    for (int nt = 0; nt < 4; nt++)
                        mma16816(acc[mt][nt],
                                 a[mt][0], a[mt][1], a[mt][2], a[mt][3],
                                 bbuf[pb][nt >> 1][(nt & 1) * 2],
                                 bbuf[pb][nt >> 1][(nt & 1) * 2 + 1]);
            }
        }

        // ---- epilogue for this tile (overlaps in-flight B loads of next) ----
        {
            int ntile = gy * NTPC + tile;
            if (ntile > NTILES - 1) ntile = NTILES - 1;
            const int n0 = ntile * 128;
            #pragma unroll
            for (int mt = 0; mt < 4; mt++) {
                #pragma unroll
                for (int nt = 0; nt < 4; nt++) {
                    const int n = n0 + nOff + nt * 8;
                    if (n < NE_SZ) {
                        const int m = mBase + mt * 16;
                        float2 v0, v1;
                        v0.x = fast_sigmoid(acc[mt][nt][0]);
                        v0.y = fast_sigmoid(acc[mt][nt][1]);
                        v1.x = fast_sigmoid(acc[mt][nt][2]);
                        v1.y = fast_sigmoid(acc[mt][nt][3]);
                        *reinterpret_cast<float2*>(out + (size_t)m * NE_SZ + n)       = v0;
                        *reinterpret_cast<float2*>(out + (size_t)(m + 8) * NE_SZ + n) = v1;
                    }
                    #pragma unroll
                    for (int r = 0; r < 4; r++) acc[mt][nt][r] = 0.f;
                }
            }
        }
    }
}

// ---------------------------------------------------------------------------
// Launch. Inputs: e1_idx, r_idx, t_idx, E, R, T, F0, F1, F2, F3
// ---------------------------------------------------------------------------
extern "C" void kernel_launch(void* const* d_in, const int* in_sizes, int n_in,
                              void* d_out, int out_size)
{
    const int*   e1_idx = (const int*)d_in[0];
    const int*   r_idx  = (const int*)d_in[1];
    const int*   t_idx  = (const int*)d_in[2];
    const float* E      = (const float*)d_in[3];
    const float* R      = (const float*)d_in[4];
    const float* T      = (const float*)d_in[5];
    const float* F0     = (const float*)d_in[6];
    const float* F1     = (const float*)d_in[7];
    const float* F2     = (const float*)d_in[8];
    const float* F3     = (const float*)d_in[9];
    float*       out    = (float*)d_out;

    float* F2T;
    __half *Hcat, *Ecat;
    cudaGetSymbolAddress((void**)&F2T,  g_F2T);
    cudaGetSymbolAddress((void**)&Hcat, g_Hcat);
    cudaGetSymbolAddress((void**)&Ecat, g_Ecat);

    static bool attr_set = false;
    if (!attr_set) {
        cudaFuncSetAttribute(gemm_mma_kernel,
                             cudaFuncAttributeMaxDynamicSharedMemorySize,
                             SMEM_GEMM);
        attr_set = true;
    }

    transpose_f2_kernel<<<(D_SZ * D_SZ + 255) / 256, 256>>>(F2, F2T);

    preproc_kernel<<<B_SZ / PP_ROWS, 256>>>(
        e1_idx, r_idx, t_idx, E, R, T, F0, F1, F3, F2T, Hcat);

    {
        size_t nt = (size_t)NE_PAD * KCH;
        pack_e_kernel<<<(unsigned)((nt + 255) / 256), 256>>>(E, Ecat);
    }

    dim3 grid(B_SZ / 128, NGRP);   // (8, 98), m fastest
    gemm_mma_kernel<<<grid, 256, SMEM_GEMM>>>(Hcat, Ecat, out);
}

// round 11
// speedup vs baseline: 8.3950x; 1.0268x over previous
#include <cuda_runtime.h>
#include <cuda_fp16.h>
#include <cstdint>

// Problem constants
#define B_SZ    1024
#define NE_SZ   100000
#define NE_PAD  100096          // 782 * 128
#define NTILES  782
#define D_SZ    200
#define KPAD    256             // row stride of packed operands (elements)

// Scratch
__device__ float   g_F2T[D_SZ * D_SZ];
__device__ __half  g_Hcat[B_SZ * KPAD];                 // 0.5 MB (pad cols stay 0)
__device__ __half  g_Ecat[(size_t)NE_PAD * KPAD];       // 51.2 MB

// ---------------------------------------------------------------------------
// PTX helpers (baseline sm_80-class PTX — compiles for plain sm_103)
// ---------------------------------------------------------------------------
__device__ __forceinline__ uint32_t smem_u32(const void* p) {
    uint32_t a;
    asm("{ .reg .u64 t; cvta.to.shared.u64 t, %1; cvt.u32.u64 %0, t; }"
        : "=r"(a) : "l"(p));
    return a;
}

__device__ __forceinline__ void cp_async16(uint32_t dst, const void* src) {
    asm volatile("cp.async.cg.shared.global [%0], [%1], 16;"
                 :: "r"(dst), "l"(src) : "memory");
}

__device__ __forceinline__ void ldsm4(uint32_t& r0, uint32_t& r1,
                                      uint32_t& r2, uint32_t& r3,
                                      uint32_t addr) {
    asm volatile("ldmatrix.sync.aligned.m8n8.x4.shared.b16 {%0,%1,%2,%3}, [%4];"
                 : "=r"(r0), "=r"(r1), "=r"(r2), "=r"(r3) : "r"(addr));
}

__device__ __forceinline__ void mma16816(float* c,
                                         uint32_t a0, uint32_t a1,
                                         uint32_t a2, uint32_t a3,
                                         uint32_t b0, uint32_t b1) {
    asm volatile(
        "mma.sync.aligned.m16n8k16.row.col.f32.f16.f16.f32 "
        "{%0,%1,%2,%3}, {%4,%5,%6,%7}, {%8,%9}, {%0,%1,%2,%3};"
        : "+f"(c[0]), "+f"(c[1]), "+f"(c[2]), "+f"(c[3])
        : "r"(a0), "r"(a1), "r"(a2), "r"(a3), "r"(b0), "r"(b1));
}

__device__ __forceinline__ uint32_t swz(uint32_t off) {
    return off ^ ((off >> 3) & 0x70);
}

// sigmoid(x) = 0.5*tanh(0.5x) + 0.5 : 1 MUFU + fma-pipe ops
__device__ __forceinline__ float fast_sigmoid(float x) {
    float t;
    asm("tanh.approx.f32 %0, %1;" : "=f"(t) : "f"(x * 0.5f));
    return fmaf(0.5f, t, 0.5f);
}

#define GROUP_BAR(id) \
    asm volatile("bar.sync %0, %1;" :: "r"(id), "r"(128) : "memory")

// ---------------------------------------------------------------------------
// Kernel 1: fused pack(E)->Ecat + transpose(F2)->F2T.
// Blocks [0, PK_BLOCKS) pack E; blocks [PK_BLOCKS, PK_BLOCKS+TR_BLOCKS) transpose.
// ---------------------------------------------------------------------------
#define KCH 26   // 208/8 column-chunks per row
#define PK_BLOCKS ((int)(((size_t)NE_PAD * KCH) / 256))      // 10166 exact
#define TR_BLOCKS ((D_SZ * D_SZ + 255) / 256)                // 157

__global__ __launch_bounds__(256)
void prep_kernel(const float* __restrict__ E, __half* __restrict__ Ecat,
                 const float* __restrict__ F2, float* __restrict__ F2T)
{
    if (blockIdx.x >= PK_BLOCKS) {
        int idx = (blockIdx.x - PK_BLOCKS) * 256 + threadIdx.x;
        if (idx < D_SZ * D_SZ) {
            int p = idx / D_SZ;
            int j = idx - p * D_SZ;
            F2T[idx] = F2[j * D_SZ + p];
        }
        return;
    }
    size_t t = (size_t)blockIdx.x * 256 + threadIdx.x;
    int row = (int)(t / KCH);
    int k0  = (int)(t % KCH) * 8;
    __half* dst = Ecat + (size_t)row * KPAD + k0;
    if (row < NE_SZ && k0 < D_SZ) {
        float4 x0 = *reinterpret_cast<const float4*>(E + (size_t)row * D_SZ + k0);
        float4 x1 = *reinterpret_cast<const float4*>(E + (size_t)row * D_SZ + k0 + 4);
        __half o[8] = {
            __float2half_rn(x0.x), __float2half_rn(x0.y),
            __float2half_rn(x0.z), __float2half_rn(x0.w),
            __float2half_rn(x1.x), __float2half_rn(x1.y),
            __float2half_rn(x1.z), __float2half_rn(x1.w)};
        *reinterpret_cast<uint4*>(dst) = *reinterpret_cast<uint4*>(o);
    } else {
        *reinterpret_cast<uint4*>(dst) = make_uint4(0, 0, 0, 0);
    }
}

// ---------------------------------------------------------------------------
// Kernel 2: preprocessing -> Hcat (fp16, cols 0..199; pad cols stay zero-init)
// ---------------------------------------------------------------------------
#define PP_ROWS 4

__global__ __launch_bounds__(256)
void preproc_kernel(const int* __restrict__ e1_idx,
                    const int* __restrict__ r_idx,
                    const int* __restrict__ t_idx,
                    const float* __restrict__ E,
                    const float* __restrict__ R,
                    const float* __restrict__ T,
                    const float* __restrict__ F0,
                    const float* __restrict__ F1,
                    const float* __restrict__ F3,
                    const float* __restrict__ F2T,
                    __half* __restrict__ Hcat)
{
    __shared__ float sE[PP_ROWS][D_SZ];
    __shared__ float sR[PP_ROWS][D_SZ];
    __shared__ float sT[PP_ROWS][D_SZ];
    __shared__ float sG[PP_ROWS][D_SZ];

    const int b0  = blockIdx.x * PP_ROWS;
    const int tid = threadIdx.x;

    for (int r = 0; r < PP_ROWS; r++) {
        const int be = e1_idx[b0 + r];
        const int br = r_idx[b0 + r];
        const int bt = t_idx[b0 + r];
        for (int k = tid; k < D_SZ; k += 256) {
            sE[r][k] = E[(size_t)be * D_SZ + k];
            sR[r][k] = R[(size_t)br * D_SZ + k];
            sT[r][k] = T[(size_t)bt * D_SZ + k];
        }
    }
    __syncthreads();

    for (int task = tid; task < PP_ROWS * D_SZ; task += 256) {
        const int r = task / D_SZ;
        const int p = task - r * D_SZ;
        float fr = 0.f, fe = 0.f, ft = 0.f;
        #pragma unroll 8
        for (int k = 0; k < D_SZ; k++) {
            fr = fmaf(sR[r][k], F0[k * D_SZ + p], fr);
            fe = fmaf(sE[r][k], F1[k * D_SZ + p], fe);
            ft = fmaf(sT[r][k], F3[k * D_SZ + p], ft);
        }
        sG[r][p] = fr * fe * ft;
    }
    __syncthreads();

    for (int task = tid; task < PP_ROWS * D_SZ; task += 256) {
        const int r = task / D_SZ;
        const int j = task - r * D_SZ;
        float acc = 0.f;
        const float* g = sG[r];
        #pragma unroll 8
        for (int p = 0; p < D_SZ; p++)
            acc = fmaf(g[p], F2T[p * D_SZ + j], acc);
        Hcat[(size_t)(b0 + r) * KPAD + j] = __float2half_rn(acc);
    }
}

// ---------------------------------------------------------------------------
// Kernel 3: x = sigmoid(Hcat @ Ecat^T), warp-level fp16 mma.sync.
// A-resident (128 M-rows, CTA-shared, loaded once). 8 warps split into TWO
// independent 4-warp groups; group g owns n-half [n0+64g, n0+64g+64) with a
// private 3-stage B ring (3 x 8 KB) and a private named barrier -> barrier
// shadows no longer cover the whole CTA. NTPC=8 tiles, K eff = 208.
// ---------------------------------------------------------------------------
#define NTPC      8
#define NGRP      98                 // 98*8 = 784 >= 782 (clamped dup tiles)
#define A_BYTES   (4 * 16384)        // 64 KB (4 chunk slots of 128 rows x 128B)
#define BG_STAGE  8192               // 64 rows x 128B per group stage
#define SMEM_GEMM (A_BYTES + 2 * 3 * BG_STAGE)   // 112 KB -> 2 CTAs/SM

// group-local B chunk load: 64 rows of Ecat, chunk kt (cols kt*64..)
__device__ __forceinline__ void load_B_g(uint32_t sB,
                                         const __half* __restrict__ Ec,
                                         int nrow0, int kt, int ltid)
{
    const char* base = (const char*)Ec + (size_t)nrow0 * (KPAD * 2) + kt * 128;
    if (kt < 3) {
        #pragma unroll
        for (int i = 0; i < 4; i++) {          // 64 rows x 8 chunks
            int task = ltid + i * 128;
            int row = task >> 3, ch = task & 7;
            cp_async16(sB + swz(row * 128 + ch * 16),
                       base + (size_t)row * (KPAD * 2) + ch * 16);
        }
    } else {                                   // partial: 64 rows x 2 chunks
        int row = ltid >> 1, ch = ltid & 1;
        cp_async16(sB + swz(row * 128 + ch * 16),
                   base + (size_t)row * (KPAD * 2) + ch * 16);
    }
    asm volatile("cp.async.commit_group;" ::: "memory");
}

__global__ __launch_bounds__(256, 2)
void gemm_mma_kernel(const __half* __restrict__ Hc,
                     const __half* __restrict__ Ec,
                     float* __restrict__ out)
{
    extern __shared__ char smem[];
    const uint32_t sb     = smem_u32(smem);
    const uint32_t sAbase = sb;

    const int tid   = threadIdx.x;
    const int wid   = tid >> 5;
    const int lane  = tid & 31;
    const int group = wid >> 2;            // 0 or 1
    const int gwid  = wid & 3;             // warp within group
    const int ltid  = tid & 127;           // thread within group
    const int warp_m = gwid & 1;           // 2 warps along M (64 rows)
    const int warp_n = gwid >> 1;          // 2 warps along N (32 cols of 64)
    const int m0 = blockIdx.x * 128;       // 8 m-CTAs fastest -> share B strip in L2
    const int gy = blockIdx.y;             // 98 n-groups of NTPC tiles
    const int nbar = 1 + group;

    const uint32_t sBg = sb + A_BYTES + group * (3 * BG_STAGE);

    // ---- A resident load: chunks 0-2 full + chunk 3 slots {0,1} (52 KB) ----
    #pragma unroll
    for (int i = 0; i < 13; i++) {
        int task = tid + i * 256;          // 0..3327
        int ktc, r, ch;
        if (task < 3072) { ktc = task >> 10; r = (task >> 3) & 127; ch = task & 7; }
        else             { int t2 = task - 3072; ktc = 3; r = t2 >> 1; ch = t2 & 1; }
        cp_async16(sAbase + ktc * 16384 + swz(r * 128 + ch * 16),
                   (const char*)Hc + (size_t)(m0 + r) * (KPAD * 2) + ktc * 128 + ch * 16);
    }
    asm volatile("cp.async.commit_group;" ::: "memory");

    // ---- B prologue: chunks 0,1 of first tile (group-local half) ----
    {
        int nt0 = gy * NTPC;           if (nt0 > NTILES - 1) nt0 = NTILES - 1;
        const int nrow0 = nt0 * 128 + group * 64;
        load_B_g(sBg + 0 * BG_STAGE, Ec, nrow0, 0, ltid);
        load_B_g(sBg + 1 * BG_STAGE, Ec, nrow0, 1, ltid);
    }

    // A done (all but the 2 most recent groups) -> full barrier for visibility
    asm volatile("cp.async.wait_group 2;" ::: "memory");
    __syncthreads();

    // fragment addressing (within-chunk byte offsets)
    uint32_t aRowOff[4], aSwb[4];
    {
        const int rbase = warp_m * 64 + (lane & 15);
        #pragma unroll
        for (int mt = 0; mt < 4; mt++) {
            int row = rbase + mt * 16;
            aRowOff[mt] = row * 128;
            aSwb[mt]    = (row & 7) * 16;
        }
    }
    const uint32_t aKhalf = (lane >> 4) * 16;

    uint32_t bRowOff[2], bSwb[2];
    {
        const int rbase = warp_n * 32 + ((lane >> 4) << 3) + (lane & 7);
        #pragma unroll
        for (int g = 0; g < 2; g++) {
            int row = rbase + g * 16;    // < 64
            bRowOff[g] = row * 128;
            bSwb[g]    = (row & 7) * 16;
        }
    }
    const uint32_t bKhalf = ((lane >> 3) & 1) * 16;

    float acc[4][4][4];
    #pragma unroll
    for (int mt = 0; mt < 4; mt++)
        #pragma unroll
        for (int nt = 0; nt < 4; nt++)
            #pragma unroll
            for (int r = 0; r < 4; r++) acc[mt][nt][r] = 0.f;

    const int mBase = m0 + warp_m * 64 + (lane >> 2);
    const int nOff  = warp_n * 32 + (lane & 3) * 2;

    #pragma unroll 1
    for (int tile = 0; tile < NTPC; tile++) {
        #pragma unroll
        for (int kt = 0; kt < 4; kt++) {
            const int c = tile * 4 + kt;

            if (c < NTPC * 4 - 1)
                asm volatile("cp.async.wait_group 1;" ::: "memory");
            else
                asm volatile("cp.async.wait_group 0;" ::: "memory");
            GROUP_BAR(nbar);

            if (c + 2 < NTPC * 4) {
                const int c2 = c + 2;
                int nt2 = gy * NTPC + (c2 >> 2);
                if (nt2 > NTILES - 1) nt2 = NTILES - 1;
                load_B_g(sBg + (c2 % 3) * BG_STAGE, Ec,
                         nt2 * 128 + group * 64, c2 & 3, ltid);
            }

            const uint32_t sAc = sAbase + kt * 16384;
            const uint32_t sBc = sBg + (c % 3) * BG_STAGE;
            const int nks = (kt < 3) ? 4 : 1;   // partial chunk: k16 only

            // B fragments double-buffered across ks steps
            uint32_t bbuf[2][2][4];
            #pragma unroll
            for (int g = 0; g < 2; g++)
                ldsm4(bbuf[0][g][0], bbuf[0][g][1], bbuf[0][g][2], bbuf[0][g][3],
                      sBc + bRowOff[g] + (bKhalf ^ bSwb[g]));

            #pragma unroll
            for (int ks = 0; ks < nks; ks++) {
                if (ks + 1 < nks) {
                    const uint32_t kcn = (ks + 1) * 32;
                    #pragma unroll
                    for (int g = 0; g < 2; g++)
                        ldsm4(bbuf[(ks + 1) & 1][g][0], bbuf[(ks + 1) & 1][g][1],
                              bbuf[(ks + 1) & 1][g][2], bbuf[(ks + 1) & 1][g][3],
                              sBc + bRowOff[g] + ((kcn + bKhalf) ^ bSwb[g]));
                }

                const uint32_t kcol = ks * 32;
                uint32_t a[4][4];
                #pragma unroll
                for (int mt = 0; mt < 4; mt++)
                    ldsm4(a[mt][0], a[mt][1], a[mt][2], a[mt][3],
                          sAc + aRowOff[mt] + ((kcol + aKhalf) ^ aSwb[mt]));

                const int pb = ks & 1;
                #pragma unroll
                for (int mt = 0; mt < 4; mt++)
                    #pragma unroll
                    for (int nt = 0; nt < 4; nt++)
                        mma16816(acc[mt][nt],
                                 a[mt][0], a[mt][1], a[mt][2], a[mt][3],
                                 bbuf[pb][nt >> 1][(nt & 1) * 2],
                                 bbuf[pb][nt >> 1][(nt & 1) * 2 + 1]);
            }
        }

        // ---- epilogue for this tile (overlaps in-flight B loads of next) ----
        {
            int ntile = gy * NTPC + tile;
            if (ntile > NTILES - 1) ntile = NTILES - 1;
            const int n0 = ntile * 128 + group * 64;
            #pragma unroll
            for (int mt = 0; mt < 4; mt++) {
                #pragma unroll
                for (int nt = 0; nt < 4; nt++) {
                    const int n = n0 + nOff + nt * 8;
                    if (n < NE_SZ) {
                        const int m = mBase + mt * 16;
                        float2 v0, v1;
                        v0.x = fast_sigmoid(acc[mt][nt][0]);
                        v0.y = fast_sigmoid(acc[mt][nt][1]);
                        v1.x = fast_sigmoid(acc[mt][nt][2]);
                        v1.y = fast_sigmoid(acc[mt][nt][3]);
                        *reinterpret_cast<float2*>(out + (size_t)m * NE_SZ + n)       = v0;
                        *reinterpret_cast<float2*>(out + (size_t)(m + 8) * NE_SZ + n) = v1;
                    }
                    #pragma unroll
                    for (int r = 0; r < 4; r++) acc[mt][nt][r] = 0.f;
                }
            }
        }
    }
}

// ---------------------------------------------------------------------------
// Launch. Inputs: e1_idx, r_idx, t_idx, E, R, T, F0, F1, F2, F3
// ---------------------------------------------------------------------------
extern "C" void kernel_launch(void* const* d_in, const int* in_sizes, int n_in,
                              void* d_out, int out_size)
{
    const int*   e1_idx = (const int*)d_in[0];
    const int*   r_idx  = (const int*)d_in[1];
    const int*   t_idx  = (const int*)d_in[2];
    const float* E      = (const float*)d_in[3];
    const float* R      = (const float*)d_in[4];
    const float* T      = (const float*)d_in[5];
    const float* F0     = (const float*)d_in[6];
    const float* F1     = (const float*)d_in[7];
    const float* F2     = (const float*)d_in[8];
    const float* F3     = (const float*)d_in[9];
    float*       out    = (float*)d_out;

    float* F2T;
    __half *Hcat, *Ecat;
    cudaGetSymbolAddress((void**)&F2T,  g_F2T);
    cudaGetSymbolAddress((void**)&Hcat, g_Hcat);
    cudaGetSymbolAddress((void**)&Ecat, g_Ecat);

    static bool attr_set = false;
    if (!attr_set) {
        cudaFuncSetAttribute(gemm_mma_kernel,
                             cudaFuncAttributeMaxDynamicSharedMemorySize,
                             SMEM_GEMM);
        attr_set = true;
    }

    prep_kernel<<<PK_BLOCKS + TR_BLOCKS, 256>>>(E, Ecat, F2, F2T);

    preproc_kernel<<<B_SZ / PP_ROWS, 256>>>(
        e1_idx, r_idx, t_idx, E, R, T, F0, F1, F3, F2T, Hcat);

    dim3 grid(B_SZ / 128, NGRP);   // (8, 98), m fastest
    gemm_mma_kernel<<<grid, 256, SMEM_GEMM>>>(Hcat, Ecat, out);
}

// round 12
// speedup vs baseline: 9.8926x; 1.1784x over previous
#include <cuda_runtime.h>
#include <cuda_fp16.h>
#include <cstdint>

// Problem constants
#define B_SZ    1024
#define NE_SZ   100000
#define NE_PAD  100096          // 782 * 128
#define NTILES  782
#define D_SZ    200
#define KPAD    256             // row stride of packed operands (elements)

// Scratch
__device__ float   g_F2T[D_SZ * D_SZ];
__device__ __half  g_Hcat[B_SZ * KPAD];                 // 0.5 MB (pad cols stay 0)
__device__ __half  g_Ecat[(size_t)NE_PAD * KPAD];       // 51.2 MB

// ---------------------------------------------------------------------------
// PTX helpers (baseline sm_80-class PTX — compiles for plain sm_103)
// ---------------------------------------------------------------------------
__device__ __forceinline__ uint32_t smem_u32(const void* p) {
    uint32_t a;
    asm("{ .reg .u64 t; cvta.to.shared.u64 t, %1; cvt.u32.u64 %0, t; }"
        : "=r"(a) : "l"(p));
    return a;
}

__device__ __forceinline__ void cp_async16(uint32_t dst, const void* src) {
    asm volatile("cp.async.cg.shared.global [%0], [%1], 16;"
                 :: "r"(dst), "l"(src) : "memory");
}

__device__ __forceinline__ void ldsm4(uint32_t& r0, uint32_t& r1,
                                      uint32_t& r2, uint32_t& r3,
                                      uint32_t addr) {
    asm volatile("ldmatrix.sync.aligned.m8n8.x4.shared.b16 {%0,%1,%2,%3}, [%4];"
                 : "=r"(r0), "=r"(r1), "=r"(r2), "=r"(r3) : "r"(addr));
}

__device__ __forceinline__ void mma16816(float* c,
                                         uint32_t a0, uint32_t a1,
                                         uint32_t a2, uint32_t a3,
                                         uint32_t b0, uint32_t b1) {
    asm volatile(
        "mma.sync.aligned.m16n8k16.row.col.f32.f16.f16.f32 "
        "{%0,%1,%2,%3}, {%4,%5,%6,%7}, {%8,%9}, {%0,%1,%2,%3};"
        : "+f"(c[0]), "+f"(c[1]), "+f"(c[2]), "+f"(c[3])
        : "r"(a0), "r"(a1), "r"(a2), "r"(a3), "r"(b0), "r"(b1));
}

__device__ __forceinline__ uint32_t swz(uint32_t off) {
    return off ^ ((off >> 3) & 0x70);
}

// sigmoid(x) = 0.5*tanh(0.5x) + 0.5 : 1 MUFU + fma-pipe ops
__device__ __forceinline__ float fast_sigmoid(float x) {
    float t;
    asm("tanh.approx.f32 %0, %1;" : "=f"(t) : "f"(x * 0.5f));
    return fmaf(0.5f, t, 0.5f);
}

#define GROUP_BAR(id) \
    asm volatile("bar.sync %0, %1;" :: "r"(id), "r"(128) : "memory")

// ---------------------------------------------------------------------------
// Kernel 1: fused pack(E)->Ecat + transpose(F2)->F2T.
// ---------------------------------------------------------------------------
#define KCH 26   // 208/8 column-chunks per row
#define PK_BLOCKS ((int)(((size_t)NE_PAD * KCH) / 256))      // 10166 exact
#define TR_BLOCKS ((D_SZ * D_SZ + 255) / 256)                // 157

__global__ __launch_bounds__(256)
void prep_kernel(const float* __restrict__ E, __half* __restrict__ Ecat,
                 const float* __restrict__ F2, float* __restrict__ F2T)
{
    if (blockIdx.x >= PK_BLOCKS) {
        int idx = (blockIdx.x - PK_BLOCKS) * 256 + threadIdx.x;
        if (idx < D_SZ * D_SZ) {
            int p = idx / D_SZ;
            int j = idx - p * D_SZ;
            F2T[idx] = F2[j * D_SZ + p];
        }
        return;
    }
    size_t t = (size_t)blockIdx.x * 256 + threadIdx.x;
    int row = (int)(t / KCH);
    int k0  = (int)(t % KCH) * 8;
    __half* dst = Ecat + (size_t)row * KPAD + k0;
    if (row < NE_SZ && k0 < D_SZ) {
        float4 x0 = *reinterpret_cast<const float4*>(E + (size_t)row * D_SZ + k0);
        float4 x1 = *reinterpret_cast<const float4*>(E + (size_t)row * D_SZ + k0 + 4);
        __half o[8] = {
            __float2half_rn(x0.x), __float2half_rn(x0.y),
            __float2half_rn(x0.z), __float2half_rn(x0.w),
            __float2half_rn(x1.x), __float2half_rn(x1.y),
            __float2half_rn(x1.z), __float2half_rn(x1.w)};
        *reinterpret_cast<uint4*>(dst) = *reinterpret_cast<uint4*>(o);
    } else {
        *reinterpret_cast<uint4*>(dst) = make_uint4(0, 0, 0, 0);
    }
}

// ---------------------------------------------------------------------------
// Kernel 2: preprocessing v3 -> Hcat (fp16).
// 8 rows per block; every F-matrix load is reused for all 8 rows (LDG count
// drops 8x vs v2 — that was the hidden ~100us L2-latency bottleneck).
// Each warp owns one 32-wide p/j chunk (7 chunks, 8 warps).
// ---------------------------------------------------------------------------
#define PPR 8

__global__ __launch_bounds__(256)
void preproc_kernel(const int* __restrict__ e1_idx,
                    const int* __restrict__ r_idx,
                    const int* __restrict__ t_idx,
                    const float* __restrict__ E,
                    const float* __restrict__ R,
                    const float* __restrict__ T,
                    const float* __restrict__ F0,
                    const float* __restrict__ F1,
                    const float* __restrict__ F3,
                    const float* __restrict__ F2T,
                    __half* __restrict__ Hcat)
{
    __shared__ float sR[PPR][D_SZ];
    __shared__ float sE[PPR][D_SZ];
    __shared__ float sT[PPR][D_SZ];
    __shared__ float sG[PPR][D_SZ];

    const int b0   = blockIdx.x * PPR;
    const int tid  = threadIdx.x;
    const int warp = tid >> 5;
    const int lane = tid & 31;

    // load the 8 embedding rows (one warp per row)
    {
        const int r  = warp;
        const int be = e1_idx[b0 + r];
        const int br = r_idx[b0 + r];
        const int bt = t_idx[b0 + r];
        for (int k = lane; k < D_SZ; k += 32) {
            sE[r][k] = E[(size_t)be * D_SZ + k];
            sR[r][k] = R[(size_t)br * D_SZ + k];
            sT[r][k] = T[(size_t)bt * D_SZ + k];
        }
    }
    __syncthreads();

    // G phase: warp w handles p-chunk w (chunks 0..6); each F load feeds 8 rows
    if (warp < 7) {
        const int p  = warp * 32 + lane;
        const bool ok = (p < D_SZ);
        const int pc = ok ? p : 0;
        float aR[PPR], aE[PPR], aT[PPR];
        #pragma unroll
        for (int r = 0; r < PPR; r++) { aR[r] = 0.f; aE[r] = 0.f; aT[r] = 0.f; }
        #pragma unroll 4
        for (int k = 0; k < D_SZ; k++) {
            const float f0 = F0[k * D_SZ + pc];
            const float f1 = F1[k * D_SZ + pc];
            const float f3 = F3[k * D_SZ + pc];
            #pragma unroll
            for (int r = 0; r < PPR; r++) {
                aR[r] = fmaf(sR[r][k], f0, aR[r]);
                aE[r] = fmaf(sE[r][k], f1, aE[r]);
                aT[r] = fmaf(sT[r][k], f3, aT[r]);
            }
        }
        if (ok) {
            #pragma unroll
            for (int r = 0; r < PPR; r++)
                sG[r][p] = aR[r] * aE[r] * aT[r];
        }
    }
    __syncthreads();

    // H phase: warp w handles j-chunk w; each F2T load feeds 8 rows
    if (warp < 7) {
        const int j  = warp * 32 + lane;
        const bool ok = (j < D_SZ);
        const int jc = ok ? j : 0;
        float a[PPR];
        #pragma unroll
        for (int r = 0; r < PPR; r++) a[r] = 0.f;
        #pragma unroll 4
        for (int p = 0; p < D_SZ; p++) {
            const float f2 = F2T[p * D_SZ + jc];
            #pragma unroll
            for (int r = 0; r < PPR; r++)
                a[r] = fmaf(sG[r][p], f2, a[r]);
        }
        if (ok) {
            #pragma unroll
            for (int r = 0; r < PPR; r++)
                Hcat[(size_t)(b0 + r) * KPAD + j] = __float2half_rn(a[r]);
        }
    }
}

// ---------------------------------------------------------------------------
// Kernel 3: x = sigmoid(Hcat @ Ecat^T), warp-level fp16 mma.sync.
// A-resident; two independent 4-warp groups with private B rings + named
// barriers. NTPC=7, NGRP=112 -> 896 CTAs = 3.03 waves (was 2.65: ~20us tail).
// ---------------------------------------------------------------------------
#define NTPC      7
#define NGRP      112                // 112*7 = 784 >= 782 (2 clamped dups)
#define A_BYTES   (4 * 16384)        // 64 KB (4 chunk slots of 128 rows x 128B)
#define BG_STAGE  8192               // 64 rows x 128B per group stage
#define SMEM_GEMM (A_BYTES + 2 * 3 * BG_STAGE)   // 112 KB -> 2 CTAs/SM

__device__ __forceinline__ void load_B_g(uint32_t sB,
                                         const __half* __restrict__ Ec,
                                         int nrow0, int kt, int ltid)
{
    const char* base = (const char*)Ec + (size_t)nrow0 * (KPAD * 2) + kt * 128;
    if (kt < 3) {
        #pragma unroll
        for (int i = 0; i < 4; i++) {          // 64 rows x 8 chunks
            int task = ltid + i * 128;
            int row = task >> 3, ch = task & 7;
            cp_async16(sB + swz(row * 128 + ch * 16),
                       base + (size_t)row * (KPAD * 2) + ch * 16);
        }
    } else {                                   // partial: 64 rows x 2 chunks
        int row = ltid >> 1, ch = ltid & 1;
        cp_async16(sB + swz(row * 128 + ch * 16),
                   base + (size_t)row * (KPAD * 2) + ch * 16);
    }
    asm volatile("cp.async.commit_group;" ::: "memory");
}

__global__ __launch_bounds__(256, 2)
void gemm_mma_kernel(const __half* __restrict__ Hc,
                     const __half* __restrict__ Ec,
                     float* __restrict__ out)
{
    extern __shared__ char smem[];
    const uint32_t sb     = smem_u32(smem);
    const uint32_t sAbase = sb;

    const int tid   = threadIdx.x;
    const int wid   = tid >> 5;
    const int lane  = tid & 31;
    const int group = wid >> 2;            // 0 or 1
    const int gwid  = wid & 3;
    const int ltid  = tid & 127;
    const int warp_m = gwid & 1;
    const int warp_n = gwid >> 1;
    const int m0 = blockIdx.x * 128;
    const int gy = blockIdx.y;
    const int nbar = 1 + group;

    const uint32_t sBg = sb + A_BYTES + group * (3 * BG_STAGE);

    // ---- A resident load: chunks 0-2 full + chunk 3 slots {0,1} (52 KB) ----
    #pragma unroll
    for (int i = 0; i < 13; i++) {
        int task = tid + i * 256;          // 0..3327
        int ktc, r, ch;
        if (task < 3072) { ktc = task >> 10; r = (task >> 3) & 127; ch = task & 7; }
        else             { int t2 = task - 3072; ktc = 3; r = t2 >> 1; ch = t2 & 1; }
        cp_async16(sAbase + ktc * 16384 + swz(r * 128 + ch * 16),
                   (const char*)Hc + (size_t)(m0 + r) * (KPAD * 2) + ktc * 128 + ch * 16);
    }
    asm volatile("cp.async.commit_group;" ::: "memory");

    // ---- B prologue: chunks 0,1 of first tile (group-local half) ----
    {
        int nt0 = gy * NTPC;           if (nt0 > NTILES - 1) nt0 = NTILES - 1;
        const int nrow0 = nt0 * 128 + group * 64;
        load_B_g(sBg + 0 * BG_STAGE, Ec, nrow0, 0, ltid);
        load_B_g(sBg + 1 * BG_STAGE, Ec, nrow0, 1, ltid);
    }

    asm volatile("cp.async.wait_group 2;" ::: "memory");
    __syncthreads();

    // fragment addressing (within-chunk byte offsets)
    uint32_t aRowOff[4], aSwb[4];
    {
        const int rbase = warp_m * 64 + (lane & 15);
        #pragma unroll
        for (int mt = 0; mt < 4; mt++) {
            int row = rbase + mt * 16;
            aRowOff[mt] = row * 128;
            aSwb[mt]    = (row & 7) * 16;
        }
    }
    const uint32_t aKhalf = (lane >> 4) * 16;

    uint32_t bRowOff[2], bSwb[2];
    {
        const int rbase = warp_n * 32 + ((lane >> 4) << 3) + (lane & 7);
        #pragma unroll
        for (int g = 0; g < 2; g++) {
            int row = rbase + g * 16;
            bRowOff[g] = row * 128;
            bSwb[g]    = (row & 7) * 16;
        }
    }
    const uint32_t bKhalf = ((lane >> 3) & 1) * 16;

    float acc[4][4][4];
    #pragma unroll
    for (int mt = 0; mt < 4; mt++)
        #pragma unroll
        for (int nt = 0; nt < 4; nt++)
            #pragma unroll
            for (int r = 0; r < 4; r++) acc[mt][nt][r] = 0.f;

    const int mBase = m0 + warp_m * 64 + (lane >> 2);
    const int nOff  = warp_n * 32 + (lane & 3) * 2;

    #pragma unroll 1
    for (int tile = 0; tile < NTPC; tile++) {
        #pragma unroll
        for (int kt = 0; kt < 4; kt++) {
            const int c = tile * 4 + kt;

            if (c < NTPC * 4 - 1)
                asm volatile("cp.async.wait_group 1;" ::: "memory");
            else
                asm volatile("cp.async.wait_group 0;" ::: "memory");
            GROUP_BAR(nbar);

            if (c + 2 < NTPC * 4) {
                const int c2 = c + 2;
                int nt2 = gy * NTPC + (c2 >> 2);
                if (nt2 > NTILES - 1) nt2 = NTILES - 1;
                load_B_g(sBg + (c2 % 3) * BG_STAGE, Ec,
                         nt2 * 128 + group * 64, c2 & 3, ltid);
            }

            const uint32_t sAc = sAbase + kt * 16384;
            const uint32_t sBc = sBg + (c % 3) * BG_STAGE;
            const int nks = (kt < 3) ? 4 : 1;

            uint32_t bbuf[2][2][4];
            #pragma unroll
            for (int g = 0; g < 2; g++)
                ldsm4(bbuf[0][g][0], bbuf[0][g][1], bbuf[0][g][2], bbuf[0][g][3],
                      sBc + bRowOff[g] + (bKhalf ^ bSwb[g]));

            #pragma unroll
            for (int ks = 0; ks < nks; ks++) {
                if (ks + 1 < nks) {
                    const uint32_t kcn = (ks + 1) * 32;
                    #pragma unroll
                    for (int g = 0; g < 2; g++)
                        ldsm4(bbuf[(ks + 1) & 1][g][0], bbuf[(ks + 1) & 1][g][1],
                              bbuf[(ks + 1) & 1][g][2], bbuf[(ks + 1) & 1][g][3],
                              sBc + bRowOff[g] + ((kcn + bKhalf) ^ bSwb[g]));
                }

                const uint32_t kcol = ks * 32;
                uint32_t a[4][4];
                #pragma unroll
                for (int mt = 0; mt < 4; mt++)
                    ldsm4(a[mt][0], a[mt][1], a[mt][2], a[mt][3],
                          sAc + aRowOff[mt] + ((kcol + aKhalf) ^ aSwb[mt]));

                const int pb = ks & 1;
                #pragma unroll
                for (int mt = 0; mt < 4; mt++)
                    #pragma unroll
                    for (int nt = 0; nt < 4; nt++)
                        mma16816(acc[mt][nt],
                                 a[mt][0], a[mt][1], a[mt][2], a[mt][3],
                                 bbuf[pb][nt >> 1][(nt & 1) * 2],
                                 bbuf[pb][nt >> 1][(nt & 1) * 2 + 1]);
            }
        }

        // ---- epilogue for this tile ----
        {
            int ntile = gy * NTPC + tile;
            if (ntile > NTILES - 1) ntile = NTILES - 1;
            const int n0 = ntile * 128 + group * 64;
            #pragma unroll
            for (int mt = 0; mt < 4; mt++) {
                #pragma unroll
                for (int nt = 0; nt < 4; nt++) {
                    const int n = n0 + nOff + nt * 8;
                    if (n < NE_SZ) {
                        const int m = mBase + mt * 16;
                        float2 v0, v1;
                        v0.x = fast_sigmoid(acc[mt][nt][0]);
                        v0.y = fast_sigmoid(acc[mt][nt][1]);
                        v1.x = fast_sigmoid(acc[mt][nt][2]);
                        v1.y = fast_sigmoid(acc[mt][nt][3]);
                        *reinterpret_cast<float2*>(out + (size_t)m * NE_SZ + n)       = v0;
                        *reinterpret_cast<float2*>(out + (size_t)(m + 8) * NE_SZ + n) = v1;
                    }
                    #pragma unroll
                    for (int r = 0; r < 4; r++) acc[mt][nt][r] = 0.f;
                }
            }
        }
    }
}

// ---------------------------------------------------------------------------
// Launch. Inputs: e1_idx, r_idx, t_idx, E, R, T, F0, F1, F2, F3
// ---------------------------------------------------------------------------
extern "C" void kernel_launch(void* const* d_in, const int* in_sizes, int n_in,
                              void* d_out, int out_size)
{
    const int*   e1_idx = (const int*)d_in[0];
    const int*   r_idx  = (const int*)d_in[1];
    const int*   t_idx  = (const int*)d_in[2];
    const float* E      = (const float*)d_in[3];
    const float* R      = (const float*)d_in[4];
    const float* T      = (const float*)d_in[5];
    const float* F0     = (const float*)d_in[6];
    const float* F1     = (const float*)d_in[7];
    const float* F2     = (const float*)d_in[8];
    const float* F3     = (const float*)d_in[9];
    float*       out    = (float*)d_out;

    float* F2T;
    __half *Hcat, *Ecat;
    cudaGetSymbolAddress((void**)&F2T,  g_F2T);
    cudaGetSymbolAddress((void**)&Hcat, g_Hcat);
    cudaGetSymbolAddress((void**)&Ecat, g_Ecat);

    static bool attr_set = false;
    if (!attr_set) {
        cudaFuncSetAttribute(gemm_mma_kernel,
                             cudaFuncAttributeMaxDynamicSharedMemorySize,
                             SMEM_GEMM);
        attr_set = true;
    }

    prep_kernel<<<PK_BLOCKS + TR_BLOCKS, 256>>>(E, Ecat, F2, F2T);

    preproc_kernel<<<B_SZ / PPR, 256>>>(
        e1_idx, r_idx, t_idx, E, R, T, F0, F1, F3, F2T, Hcat);

    dim3 grid(B_SZ / 128, NGRP);   // (8, 112), m fastest
    gemm_mma_kernel<<<grid, 256, SMEM_GEMM>>>(Hcat, Ecat, out);
}